// round 13
// baseline (speedup 1.0000x reference)
#include <cuda_runtime.h>
#include <cuda_bf16.h>

// ---------------------------------------------------------------------------
// MixingBlock: s = softmax((x Wq)(sl Wk)^T * scale) @ sl,  w = the softmax
// Restructure: dots = x @ KQ^T with KQ = scale * (sl Wk) Wq^T  (tiny [128,180])
// Pipeline (4 launches): p1 (+zero KQT) -> p2f (reduce+GEMM, atomic KQ)
//                        -> c1 (bf16 mma) -> c2 (bf16 mma, ILP-split accs)
// ---------------------------------------------------------------------------

#define NB 4
#define NR 8192
#define NS 32
#define IN_DIM 180
#define SD 1536
#define AD 1536
#define BS (NB*NS)          // 128
#define KS 16               // d-split for p1
#define KCHUNK (SD/KS)      // 96
#define AC 24               // a-chunks for p2f
#define ACHUNK (AD/AC)      // 64

typedef unsigned long long ull;
typedef unsigned int u32;

__device__ float g_kpart[KS][BS][AD];     // p1 partials
__device__ float g_KQT[IN_DIM][BS];       // KQ transposed (scale folded in)

// ---- packed f32x2 helpers -------------------------------------------------
__device__ __forceinline__ ull fpack(float x, float y) {
    ull r; asm("mov.b64 %0, {%1, %2};" : "=l"(r) : "f"(x), "f"(y)); return r;
}
__device__ __forceinline__ float2 funpack(ull v) {
    float2 r; asm("mov.b64 {%0, %1}, %2;" : "=f"(r.x), "=f"(r.y) : "l"(v)); return r;
}
__device__ __forceinline__ ull ffma2(ull a, ull b, ull c) {
    ull d; asm("fma.rn.f32x2 %0, %1, %2, %3;" : "=l"(d) : "l"(a), "l"(b), "l"(c)); return d;
}
__device__ __forceinline__ ull d2u(double d) { return __double_as_longlong(d); }
__device__ __forceinline__ double u2d(ull v) { return __longlong_as_double(v); }

// ---- bf16 helpers ---------------------------------------------------------
__device__ __forceinline__ u32 packbf2(float x, float y) {
    __nv_bfloat162 t = __floats2bfloat162_rn(x, y);
    return *reinterpret_cast<u32*>(&t);
}
__device__ __forceinline__ float bf16rt(float v) {
    return __bfloat162float(__float2bfloat16_rn(v));
}
__device__ __forceinline__ void mma16816(float c[4], const u32 a[4], const u32 b[2]) {
    asm volatile(
        "mma.sync.aligned.m16n8k16.row.col.f32.bf16.bf16.f32 "
        "{%0,%1,%2,%3},{%4,%5,%6,%7},{%8,%9},{%0,%1,%2,%3};"
        : "+f"(c[0]), "+f"(c[1]), "+f"(c[2]), "+f"(c[3])
        : "r"(a[0]), "r"(a[1]), "r"(a[2]), "r"(a[3]), "r"(b[0]), "r"(b[1]));
}

// ---------------------------------------------------------------------------
// P1: g_kpart[p][m][n] = sum_{d in chunk p} sl[m][d] * Wk[d][n]
// Block (0,0,0) additionally zeroes g_KQT (p2f accumulates atomically).
// ---------------------------------------------------------------------------
__global__ __launch_bounds__(128) void p1_kernel(const float* __restrict__ sl,
                                                 const float* __restrict__ Wk) {
    const int n0 = blockIdx.x * 256;
    const int m0 = blockIdx.y * 32;
    const int p  = blockIdx.z;
    const int d0 = p * KCHUNK;
    __shared__ float sWk[16][256];
    __shared__ ull   sslp[16][33];
    const int tid  = threadIdx.x;
    const int warp = tid >> 5, lane = tid & 31;
    const int mbase = warp * 8;

    if (blockIdx.x == 0 && blockIdx.y == 0 && blockIdx.z == 0) {
        float4 z = make_float4(0.f, 0.f, 0.f, 0.f);
        for (int idx = tid; idx < (IN_DIM * BS) / 4; idx += 128)
            ((float4*)&g_KQT[0][0])[idx] = z;
    }

    ull acc[8][4];
    #pragma unroll
    for (int i = 0; i < 8; i++)
        #pragma unroll
        for (int q = 0; q < 4; q++) acc[i][q] = 0ULL;

    for (int kk = 0; kk < KCHUNK; kk += 16) {
        __syncthreads();
        #pragma unroll
        for (int t = 0; t < 8; t++) {
            int idx = t * 128 + tid;
            int dd = idx >> 6, nq = idx & 63;
            *(float4*)&sWk[dd][nq * 4] =
                *(const float4*)&Wk[(size_t)(d0 + kk + dd) * AD + n0 + nq * 4];
        }
        #pragma unroll
        for (int t = 0; t < 4; t++) {
            int idx = t * 128 + tid;
            int m = idx >> 4, dd = idx & 15;
            float v = sl[(size_t)(m0 + m) * SD + d0 + kk + dd];
            sslp[dd][m] = fpack(v, v);
        }
        __syncthreads();
        #pragma unroll
        for (int dd = 0; dd < 16; dd++) {
            double2 a01 = *(const double2*)&sWk[dd][lane * 4];
            double2 a23 = *(const double2*)&sWk[dd][128 + lane * 4];
            ull A0 = d2u(a01.x), A1 = d2u(a01.y), A2 = d2u(a23.x), A3 = d2u(a23.y);
            #pragma unroll
            for (int i = 0; i < 8; i++) {
                ull wv = sslp[dd][mbase + i];
                acc[i][0] = ffma2(A0, wv, acc[i][0]);
                acc[i][1] = ffma2(A1, wv, acc[i][1]);
                acc[i][2] = ffma2(A2, wv, acc[i][2]);
                acc[i][3] = ffma2(A3, wv, acc[i][3]);
            }
        }
    }
    #pragma unroll
    for (int i = 0; i < 8; i++) {
        int m = m0 + mbase + i;
        float* dst = &g_kpart[p][m][n0 + lane * 4];
        *(double2*)dst         = make_double2(u2d(acc[i][0]), u2d(acc[i][1]));
        *(double2*)(dst + 128) = make_double2(u2d(acc[i][2]), u2d(acc[i][3]));
    }
}

// ---------------------------------------------------------------------------
// P2F (fused p1r+p2): per (a-chunk, m-half) block: reduce the 16 kpart
// partials into smem (transposed), then KQT[j][m] += scale*sum_a k[m][a]Wq[j][a]
// over all 180 j in 6 passes of 32. grid (24, 2), 256 thr.
// ---------------------------------------------------------------------------
__global__ __launch_bounds__(256) void p2f_kernel(const float* __restrict__ Wq) {
    const int a0 = blockIdx.x * ACHUNK;    // 64-wide a-chunk
    const int m0 = blockIdx.y * 64;        // m-half
    __shared__ __align__(16) float ksm[64][72];   // [a][m], stride 72 (8B-aligned rows)
    __shared__ ull wqs[64][34];                   // splatted Wq, 16B-aligned rows
    const int tid = threadIdx.x;

    // phase 1: reduce kpart -> ksm (transposed). m = tid&63 -> contiguous STS.
    #pragma unroll
    for (int t = 0; t < 4; t++) {
        int aq = t * 4 + (tid >> 6);       // 0..15
        int m  = tid & 63;
        float4 a = make_float4(0.f, 0.f, 0.f, 0.f);
        #pragma unroll
        for (int p = 0; p < KS; p++) {
            float4 v = *(const float4*)&g_kpart[p][m0 + m][a0 + aq * 4];
            a.x += v.x; a.y += v.y; a.z += v.z; a.w += v.w;
        }
        ksm[aq * 4 + 0][m] = a.x;
        ksm[aq * 4 + 1][m] = a.y;
        ksm[aq * 4 + 2][m] = a.z;
        ksm[aq * 4 + 3][m] = a.w;
    }

    const float scale = rsqrtf((float)AD);
    const int mp = tid & 31;               // m-pair: m = 2*mp (local)
    const int jg = tid >> 5;               // 0..7

    for (int pass = 0; pass < 6; pass++) {
        __syncthreads();                   // ksm ready / wqs reuse safe
        #pragma unroll
        for (int t = 0; t < 8; t++) {
            int idx = t * 256 + tid;
            int jj = idx >> 6, a = idx & 63;
            int j = pass * 32 + jj;
            float v = (j < IN_DIM) ? Wq[(size_t)j * AD + a0 + a] * scale : 0.f;
            wqs[a][jj] = fpack(v, v);
        }
        __syncthreads();

        ull acc[4] = {0ULL, 0ULL, 0ULL, 0ULL};
        #pragma unroll 4
        for (int a = 0; a < ACHUNK; a++) {
            ull kp = *(const ull*)&ksm[a][2 * mp];
            double2 w01 = *(const double2*)&wqs[a][jg * 4];
            double2 w23 = *(const double2*)&wqs[a][jg * 4 + 2];
            acc[0] = ffma2(kp, d2u(w01.x), acc[0]);
            acc[1] = ffma2(kp, d2u(w01.y), acc[1]);
            acc[2] = ffma2(kp, d2u(w23.x), acc[2]);
            acc[3] = ffma2(kp, d2u(w23.y), acc[3]);
        }
        #pragma unroll
        for (int q = 0; q < 4; q++) {
            int j = pass * 32 + jg * 4 + q;
            if (j < IN_DIM) {
                float2 v = funpack(acc[q]);
                atomicAdd(&g_KQT[j][m0 + 2 * mp], v.x);
                atomicAdd(&g_KQT[j][m0 + 2 * mp + 1], v.y);
            }
        }
    }
}

// ---------------------------------------------------------------------------
// C1 (tensor core): dots = x @ KQ (K=180 pad 192), softmax, write w.
// (unchanged from the 123.4us run)
// ---------------------------------------------------------------------------
#define C1_SMEM 76800
__global__ __launch_bounds__(128, 2) void c1_kernel(const float* __restrict__ x,
                                                    float* __restrict__ w_out) {
    extern __shared__ u32 c1sm[];
    u32* xhi = c1sm;                 // [64][100]
    u32* xlo = c1sm + 6400;          // [64][100]
    u32* khi = c1sm + 12800;         // [32][100]
    u32* klo = c1sm + 16000;         // [32][100]

    const int row0 = blockIdx.x * 64;
    const int b = row0 >> 13;
    const int tid = threadIdx.x;

    for (int idx = tid; idx < 64 * 45; idx += 128) {
        int r = idx / 45, q = idx - r * 45;
        float4 v = *(const float4*)&x[(size_t)(row0 + r) * IN_DIM + q * 4];
        float h0 = bf16rt(v.x), h1 = bf16rt(v.y);
        float h2 = bf16rt(v.z), h3 = bf16rt(v.w);
        xhi[r * 100 + 2 * q]     = packbf2(h0, h1);
        xhi[r * 100 + 2 * q + 1] = packbf2(h2, h3);
        xlo[r * 100 + 2 * q]     = packbf2(v.x - h0, v.y - h1);
        xlo[r * 100 + 2 * q + 1] = packbf2(v.z - h2, v.w - h3);
    }
    for (int idx = tid; idx < 64 * 6; idx += 128) {
        int r = idx / 6, jp = 90 + idx - (idx / 6) * 6;
        xhi[r * 100 + jp] = 0u;
        xlo[r * 100 + jp] = 0u;
    }
    for (int idx = tid; idx < NS * 96; idx += 128) {
        int s = idx & 31, jp = idx >> 5;
        float f0 = (2 * jp     < IN_DIM) ? g_KQT[2 * jp][b * NS + s]     : 0.f;
        float f1 = (2 * jp + 1 < IN_DIM) ? g_KQT[2 * jp + 1][b * NS + s] : 0.f;
        float h0 = bf16rt(f0), h1 = bf16rt(f1);
        khi[s * 100 + jp] = packbf2(h0, h1);
        klo[s * 100 + jp] = packbf2(f0 - h0, f1 - h1);
    }
    __syncthreads();

    const int warp = tid >> 5, lane = tid & 31;
    const int gid = lane >> 2, tig = lane & 3;
    const int wr = warp * 16;

    float c[4][4];
    #pragma unroll
    for (int nt = 0; nt < 4; nt++)
        #pragma unroll
        for (int q = 0; q < 4; q++) c[nt][q] = 0.f;

    #pragma unroll
    for (int kt = 0; kt < 12; kt++) {
        const int pb = kt * 8;
        u32 Ah[4], Al[4];
        Ah[0] = xhi[(wr + gid    ) * 100 + pb + tig];
        Ah[1] = xhi[(wr + gid + 8) * 100 + pb + tig];
        Ah[2] = xhi[(wr + gid    ) * 100 + pb + tig + 4];
        Ah[3] = xhi[(wr + gid + 8) * 100 + pb + tig + 4];
        Al[0] = xlo[(wr + gid    ) * 100 + pb + tig];
        Al[1] = xlo[(wr + gid + 8) * 100 + pb + tig];
        Al[2] = xlo[(wr + gid    ) * 100 + pb + tig + 4];
        Al[3] = xlo[(wr + gid + 8) * 100 + pb + tig + 4];
        #pragma unroll
        for (int nt = 0; nt < 4; nt++) {
            const int n = nt * 8 + gid;
            u32 Bh[2] = { khi[n * 100 + pb + tig], khi[n * 100 + pb + tig + 4] };
            u32 Bl[2] = { klo[n * 100 + pb + tig], klo[n * 100 + pb + tig + 4] };
            mma16816(c[nt], Ah, Bh);
            mma16816(c[nt], Ah, Bl);
            mma16816(c[nt], Al, Bh);
        }
    }

    float m0 = -1e30f, m1 = -1e30f;
    #pragma unroll
    for (int nt = 0; nt < 4; nt++) {
        m0 = fmaxf(m0, fmaxf(c[nt][0], c[nt][1]));
        m1 = fmaxf(m1, fmaxf(c[nt][2], c[nt][3]));
    }
    m0 = fmaxf(m0, __shfl_xor_sync(0xffffffffu, m0, 1));
    m0 = fmaxf(m0, __shfl_xor_sync(0xffffffffu, m0, 2));
    m1 = fmaxf(m1, __shfl_xor_sync(0xffffffffu, m1, 1));
    m1 = fmaxf(m1, __shfl_xor_sync(0xffffffffu, m1, 2));

    float e[4][4];
    float s0 = 0.f, s1 = 0.f;
    #pragma unroll
    for (int nt = 0; nt < 4; nt++) {
        e[nt][0] = __expf(c[nt][0] - m0);
        e[nt][1] = __expf(c[nt][1] - m0);
        e[nt][2] = __expf(c[nt][2] - m1);
        e[nt][3] = __expf(c[nt][3] - m1);
        s0 += e[nt][0] + e[nt][1];
        s1 += e[nt][2] + e[nt][3];
    }
    s0 += __shfl_xor_sync(0xffffffffu, s0, 1);
    s0 += __shfl_xor_sync(0xffffffffu, s0, 2);
    s1 += __shfl_xor_sync(0xffffffffu, s1, 1);
    s1 += __shfl_xor_sync(0xffffffffu, s1, 2);
    float i0 = 1.0f / s0, i1 = 1.0f / s1;

    #pragma unroll
    for (int nt = 0; nt < 4; nt++) {
        const int n = nt * 8 + tig * 2;
        *(float2*)&w_out[(size_t)(row0 + wr + gid    ) * NS + n] =
            make_float2(e[nt][0] * i0, e[nt][1] * i0);
        *(float2*)&w_out[(size_t)(row0 + wr + gid + 8) * NS + n] =
            make_float2(e[nt][2] * i1, e[nt][3] * i1);
    }
}

// ---------------------------------------------------------------------------
// C2 (tensor core): s = w @ sl via mma.m16n8k16 bf16 3-term split.
// NEW: 3 independent accumulator chains (hh/hl/lh) -> mma ILP x3;
// smem back to 30KB (no stage), launch_bounds(256,4) -> 32 warps/SM.
// ---------------------------------------------------------------------------
#define C2_SMEM 30720
__global__ __launch_bounds__(256, 4) void c2_kernel(const float* __restrict__ sl,
                                                    const float* __restrict__ w_in,
                                                    float* __restrict__ s_out) {
    extern __shared__ u32 c2sm[];
    u32* slT_hi = c2sm;              // [128][20]
    u32* slT_lo = c2sm + 2560;       // [128][20]
    u32* whi    = c2sm + 5120;       // [64][20]
    u32* wlo    = c2sm + 6400;       // [64][20]

    const int d0   = blockIdx.x * 128;
    const int row0 = blockIdx.y * 64;
    const int b    = row0 >> 13;
    const int tid  = threadIdx.x;

    #pragma unroll
    for (int t = 0; t < 8; t++) {
        int idx = t * 256 + tid;
        int q = idx >> 7, d = idx & 127;
        const float* base = &sl[(size_t)(b * NS + 2 * q) * SD + d0 + d];
        float v0 = base[0], v1 = base[SD];
        float h0 = bf16rt(v0), h1 = bf16rt(v1);
        slT_hi[d * 20 + q] = packbf2(h0, h1);
        slT_lo[d * 20 + q] = packbf2(v0 - h0, v1 - h1);
    }
    #pragma unroll
    for (int t = 0; t < 4; t++) {
        int idx = t * 256 + tid;
        int r = idx >> 4, q = idx & 15;
        const float* wb = &w_in[(size_t)(row0 + r) * NS + 2 * q];
        float v0 = wb[0], v1 = wb[1];
        float h0 = bf16rt(v0), h1 = bf16rt(v1);
        whi[r * 20 + q] = packbf2(h0, h1);
        wlo[r * 20 + q] = packbf2(v0 - h0, v1 - h1);
    }
    __syncthreads();

    const int warp = tid >> 5, lane = tid & 31;
    const int gid = lane >> 2, tig = lane & 3;
    const int wr = (warp >> 1) * 16;
    const int wd = (warp & 1) * 64;

    u32 Ahi[8], Alo[8];
    #pragma unroll
    for (int k = 0; k < 2; k++) {
        int pb = k * 8;
        Ahi[k*4+0] = whi[(wr + gid    ) * 20 + pb + tig    ];
        Ahi[k*4+1] = whi[(wr + gid + 8) * 20 + pb + tig    ];
        Ahi[k*4+2] = whi[(wr + gid    ) * 20 + pb + tig + 4];
        Ahi[k*4+3] = whi[(wr + gid + 8) * 20 + pb + tig + 4];
        Alo[k*4+0] = wlo[(wr + gid    ) * 20 + pb + tig    ];
        Alo[k*4+1] = wlo[(wr + gid + 8) * 20 + pb + tig    ];
        Alo[k*4+2] = wlo[(wr + gid    ) * 20 + pb + tig + 4];
        Alo[k*4+3] = wlo[(wr + gid + 8) * 20 + pb + tig + 4];
    }

    #pragma unroll
    for (int nt = 0; nt < 8; nt++) {
        const int dcol = wd + nt * 8 + gid;
        u32 Bh[4], Bl[4];
        Bh[0] = slT_hi[dcol * 20 + tig];      Bh[1] = slT_hi[dcol * 20 + tig + 4];
        Bh[2] = slT_hi[dcol * 20 + 8 + tig];  Bh[3] = slT_hi[dcol * 20 + 12 + tig];
        Bl[0] = slT_lo[dcol * 20 + tig];      Bl[1] = slT_lo[dcol * 20 + tig + 4];
        Bl[2] = slT_lo[dcol * 20 + 8 + tig];  Bl[3] = slT_lo[dcol * 20 + 12 + tig];

        // 3 independent chains (depth 2 each) -> tensor-pipe ILP x3
        float chh[4] = {0.f, 0.f, 0.f, 0.f};
        float chl[4] = {0.f, 0.f, 0.f, 0.f};
        float clh[4] = {0.f, 0.f, 0.f, 0.f};
        mma16816(chh, &Ahi[0], &Bh[0]);
        mma16816(chl, &Ahi[0], &Bl[0]);
        mma16816(clh, &Alo[0], &Bh[0]);
        mma16816(chh, &Ahi[4], &Bh[2]);
        mma16816(chl, &Ahi[4], &Bl[2]);
        mma16816(clh, &Alo[4], &Bh[2]);

        const int dg = d0 + wd + nt * 8 + tig * 2;
        float r00 = (chh[0] + chl[0]) + clh[0];
        float r01 = (chh[1] + chl[1]) + clh[1];
        float r10 = (chh[2] + chl[2]) + clh[2];
        float r11 = (chh[3] + chl[3]) + clh[3];
        *(float2*)&s_out[(size_t)(row0 + wr + gid    ) * SD + dg] = make_float2(r00, r01);
        *(float2*)&s_out[(size_t)(row0 + wr + gid + 8) * SD + dg] = make_float2(r10, r11);
    }
}

// ---------------------------------------------------------------------------
extern "C" void kernel_launch(void* const* d_in, const int* in_sizes, int n_in,
                              void* d_out, int out_size) {
    const float* x  = (const float*)d_in[0];   // [4,8192,180]
    const float* sl = (const float*)d_in[1];   // [4,32,1536]
    const float* Wq = (const float*)d_in[2];   // [180,1536]
    const float* Wk = (const float*)d_in[3];   // [1536,1536]
    float* out   = (float*)d_out;
    float* s_out = out;                               // [4,8192,1536]
    float* w_out = out + (size_t)NB * NR * SD;        // [4,8192,32]

    static int attr_done = 0;
    if (!attr_done) {
        cudaFuncSetAttribute(c1_kernel,
                             cudaFuncAttributeMaxDynamicSharedMemorySize, C1_SMEM);
        cudaFuncSetAttribute(c2_kernel,
                             cudaFuncAttributeMaxDynamicSharedMemorySize, C2_SMEM);
        attr_done = 1;
    }

    p1_kernel<<<dim3(AD / 256, BS / 32, KS), 128>>>(sl, Wk);
    p2f_kernel<<<dim3(AC, 2), 256>>>(Wq);
    c1_kernel<<<(NB * NR) / 64, 128, C1_SMEM>>>(x, w_out);
    c2_kernel<<<dim3(SD / 128, (NB * NR) / 64), 256, C2_SMEM>>>(sl, w_out, s_out);
}

// round 14
// speedup vs baseline: 1.2420x; 1.2420x over previous
#include <cuda_runtime.h>
#include <cuda_bf16.h>

// ---------------------------------------------------------------------------
// MixingBlock: s = softmax((x Wq)(sl Wk)^T * scale) @ sl,  w = the softmax
// Restructure: dots = x @ KQ^T with KQ = scale * (sl Wk) Wq^T  (tiny [128,180])
// Pipeline: p1 -> p1r (reduce + zero KQT) -> p2 (atomic KQ) -> c1 -> c2
// ---------------------------------------------------------------------------

#define NB 4
#define NR 8192
#define NS 32
#define IN_DIM 180
#define SD 1536
#define AD 1536
#define BS (NB*NS)          // 128
#define KS 16               // d-split for p1
#define KCHUNK (SD/KS)      // 96
#define AC 24               // a-chunks for p2
#define ACHUNK (AD/AC)      // 64
#define JT 16               // j-tile for p2

typedef unsigned long long ull;
typedef unsigned int u32;

__device__ float g_kpart[KS][BS][AD];     // p1 partials
__device__ float g_kred[BS][AD];          // reduced k
__device__ float g_KQT[IN_DIM][BS];       // KQ transposed (scale folded in)

// ---- packed f32x2 helpers -------------------------------------------------
__device__ __forceinline__ ull fpack(float x, float y) {
    ull r; asm("mov.b64 %0, {%1, %2};" : "=l"(r) : "f"(x), "f"(y)); return r;
}
__device__ __forceinline__ float2 funpack(ull v) {
    float2 r; asm("mov.b64 {%0, %1}, %2;" : "=f"(r.x), "=f"(r.y) : "l"(v)); return r;
}
__device__ __forceinline__ ull ffma2(ull a, ull b, ull c) {
    ull d; asm("fma.rn.f32x2 %0, %1, %2, %3;" : "=l"(d) : "l"(a), "l"(b), "l"(c)); return d;
}
__device__ __forceinline__ ull d2u(double d) { return __double_as_longlong(d); }
__device__ __forceinline__ double u2d(ull v) { return __longlong_as_double(v); }

// ---- bf16 helpers ---------------------------------------------------------
__device__ __forceinline__ u32 packbf2(float x, float y) {
    __nv_bfloat162 t = __floats2bfloat162_rn(x, y);
    return *reinterpret_cast<u32*>(&t);
}
__device__ __forceinline__ float bf16rt(float v) {
    return __bfloat162float(__float2bfloat16_rn(v));
}
__device__ __forceinline__ void mma16816(float c[4], const u32 a[4], const u32 b[2]) {
    asm volatile(
        "mma.sync.aligned.m16n8k16.row.col.f32.bf16.bf16.f32 "
        "{%0,%1,%2,%3},{%4,%5,%6,%7},{%8,%9},{%0,%1,%2,%3};"
        : "+f"(c[0]), "+f"(c[1]), "+f"(c[2]), "+f"(c[3])
        : "r"(a[0]), "r"(a[1]), "r"(a[2]), "r"(a[3]), "r"(b[0]), "r"(b[1]));
}

// ---------------------------------------------------------------------------
// P1: g_kpart[p][m][n] = sum_{d in chunk p} sl[m][d] * Wk[d][n]
// (round-12 proven version)
// ---------------------------------------------------------------------------
__global__ __launch_bounds__(128) void p1_kernel(const float* __restrict__ sl,
                                                 const float* __restrict__ Wk) {
    const int n0 = blockIdx.x * 256;
    const int m0 = blockIdx.y * 32;
    const int p  = blockIdx.z;
    const int d0 = p * KCHUNK;
    __shared__ float sWk[16][256];
    __shared__ ull   sslp[16][33];
    const int tid  = threadIdx.x;
    const int warp = tid >> 5, lane = tid & 31;
    const int mbase = warp * 8;

    ull acc[8][4];
    #pragma unroll
    for (int i = 0; i < 8; i++)
        #pragma unroll
        for (int q = 0; q < 4; q++) acc[i][q] = 0ULL;

    for (int kk = 0; kk < KCHUNK; kk += 16) {
        __syncthreads();
        #pragma unroll
        for (int t = 0; t < 8; t++) {
            int idx = t * 128 + tid;
            int dd = idx >> 6, nq = idx & 63;
            *(float4*)&sWk[dd][nq * 4] =
                *(const float4*)&Wk[(size_t)(d0 + kk + dd) * AD + n0 + nq * 4];
        }
        #pragma unroll
        for (int t = 0; t < 4; t++) {
            int idx = t * 128 + tid;
            int m = idx >> 4, dd = idx & 15;
            float v = sl[(size_t)(m0 + m) * SD + d0 + kk + dd];
            sslp[dd][m] = fpack(v, v);
        }
        __syncthreads();
        #pragma unroll
        for (int dd = 0; dd < 16; dd++) {
            double2 a01 = *(const double2*)&sWk[dd][lane * 4];
            double2 a23 = *(const double2*)&sWk[dd][128 + lane * 4];
            ull A0 = d2u(a01.x), A1 = d2u(a01.y), A2 = d2u(a23.x), A3 = d2u(a23.y);
            #pragma unroll
            for (int i = 0; i < 8; i++) {
                ull wv = sslp[dd][mbase + i];
                acc[i][0] = ffma2(A0, wv, acc[i][0]);
                acc[i][1] = ffma2(A1, wv, acc[i][1]);
                acc[i][2] = ffma2(A2, wv, acc[i][2]);
                acc[i][3] = ffma2(A3, wv, acc[i][3]);
            }
        }
    }
    #pragma unroll
    for (int i = 0; i < 8; i++) {
        int m = m0 + mbase + i;
        float* dst = &g_kpart[p][m][n0 + lane * 4];
        *(double2*)dst         = make_double2(u2d(acc[i][0]), u2d(acc[i][1]));
        *(double2*)(dst + 128) = make_double2(u2d(acc[i][2]), u2d(acc[i][3]));
    }
}

// ---------------------------------------------------------------------------
// P1R: g_kred = sum_p g_kpart[p]; also zeros g_KQT for p2's atomics.
// ---------------------------------------------------------------------------
__global__ __launch_bounds__(256) void p1r_kernel() {
    int gid = blockIdx.x * 256 + threadIdx.x;
    if (gid < IN_DIM * BS) (&g_KQT[0][0])[gid] = 0.f;
    const float4* src = (const float4*)&g_kpart[0][0][0];
    float4* dst = (float4*)&g_kred[0][0];
    const int stride = (BS * AD) / 4;
    float4 a = make_float4(0.f, 0.f, 0.f, 0.f);
    #pragma unroll
    for (int p = 0; p < KS; p++) {
        float4 v = src[(size_t)p * stride + gid];
        a.x += v.x; a.y += v.y; a.z += v.z; a.w += v.w;
    }
    dst[gid] = a;
}

// ---------------------------------------------------------------------------
// P2: g_KQT[j][m] += scale * sum_{a in chunk} kred[m][a] * Wq[j][a]
// (round-12 proven version)
// ---------------------------------------------------------------------------
__global__ __launch_bounds__(256) void p2_kernel(const float* __restrict__ Wq) {
    const int j0 = blockIdx.x * JT;
    const int ac = blockIdx.y;
    const int a0 = ac * ACHUNK;
    __shared__ float ksm[64][130];
    __shared__ ull   wqs[64][18];
    const int tid = threadIdx.x;
    const int mp = tid & 63;
    const int jg = tid >> 6;

    #pragma unroll
    for (int t = 0; t < 8; t++) {
        int idx = t * 256 + tid;
        int m = idx >> 4, aq = idx & 15;
        float4 v = *(const float4*)&g_kred[m][a0 + aq * 4];
        ksm[aq * 4 + 0][m] = v.x;
        ksm[aq * 4 + 1][m] = v.y;
        ksm[aq * 4 + 2][m] = v.z;
        ksm[aq * 4 + 3][m] = v.w;
    }
    const float scale = rsqrtf((float)AD);
    #pragma unroll
    for (int t = 0; t < 4; t++) {
        int idx = t * 256 + tid;
        int jj = idx >> 6, a = idx & 63;
        int j = j0 + jj;
        float v = (j < IN_DIM) ? Wq[(size_t)j * AD + a0 + a] * scale : 0.f;
        wqs[a][jj] = fpack(v, v);
    }
    __syncthreads();

    ull acc[4] = {0ULL, 0ULL, 0ULL, 0ULL};
    #pragma unroll 4
    for (int a = 0; a < ACHUNK; a++) {
        ull kp = *(const ull*)&ksm[a][2 * mp];
        double2 w01 = *(const double2*)&wqs[a][jg * 4];
        double2 w23 = *(const double2*)&wqs[a][jg * 4 + 2];
        acc[0] = ffma2(kp, d2u(w01.x), acc[0]);
        acc[1] = ffma2(kp, d2u(w01.y), acc[1]);
        acc[2] = ffma2(kp, d2u(w23.x), acc[2]);
        acc[3] = ffma2(kp, d2u(w23.y), acc[3]);
    }
    #pragma unroll
    for (int q = 0; q < 4; q++) {
        int j = j0 + jg * 4 + q;
        if (j < IN_DIM) {
            float2 v = funpack(acc[q]);
            atomicAdd(&g_KQT[j][2 * mp], v.x);
            atomicAdd(&g_KQT[j][2 * mp + 1], v.y);
        }
    }
}

// ---------------------------------------------------------------------------
// C1 (tensor core): dots = x @ KQ (K=180 pad 192), softmax, write w.
// (unchanged from the 123.4us run)
// ---------------------------------------------------------------------------
#define C1_SMEM 76800
__global__ __launch_bounds__(128, 2) void c1_kernel(const float* __restrict__ x,
                                                    float* __restrict__ w_out) {
    extern __shared__ u32 c1sm[];
    u32* xhi = c1sm;                 // [64][100]
    u32* xlo = c1sm + 6400;          // [64][100]
    u32* khi = c1sm + 12800;         // [32][100]
    u32* klo = c1sm + 16000;         // [32][100]

    const int row0 = blockIdx.x * 64;
    const int b = row0 >> 13;
    const int tid = threadIdx.x;

    for (int idx = tid; idx < 64 * 45; idx += 128) {
        int r = idx / 45, q = idx - r * 45;
        float4 v = *(const float4*)&x[(size_t)(row0 + r) * IN_DIM + q * 4];
        float h0 = bf16rt(v.x), h1 = bf16rt(v.y);
        float h2 = bf16rt(v.z), h3 = bf16rt(v.w);
        xhi[r * 100 + 2 * q]     = packbf2(h0, h1);
        xhi[r * 100 + 2 * q + 1] = packbf2(h2, h3);
        xlo[r * 100 + 2 * q]     = packbf2(v.x - h0, v.y - h1);
        xlo[r * 100 + 2 * q + 1] = packbf2(v.z - h2, v.w - h3);
    }
    for (int idx = tid; idx < 64 * 6; idx += 128) {
        int r = idx / 6, jp = 90 + idx - (idx / 6) * 6;
        xhi[r * 100 + jp] = 0u;
        xlo[r * 100 + jp] = 0u;
    }
    for (int idx = tid; idx < NS * 96; idx += 128) {
        int s = idx & 31, jp = idx >> 5;
        float f0 = (2 * jp     < IN_DIM) ? g_KQT[2 * jp][b * NS + s]     : 0.f;
        float f1 = (2 * jp + 1 < IN_DIM) ? g_KQT[2 * jp + 1][b * NS + s] : 0.f;
        float h0 = bf16rt(f0), h1 = bf16rt(f1);
        khi[s * 100 + jp] = packbf2(h0, h1);
        klo[s * 100 + jp] = packbf2(f0 - h0, f1 - h1);
    }
    __syncthreads();

    const int warp = tid >> 5, lane = tid & 31;
    const int gid = lane >> 2, tig = lane & 3;
    const int wr = warp * 16;

    float c[4][4];
    #pragma unroll
    for (int nt = 0; nt < 4; nt++)
        #pragma unroll
        for (int q = 0; q < 4; q++) c[nt][q] = 0.f;

    #pragma unroll
    for (int kt = 0; kt < 12; kt++) {
        const int pb = kt * 8;
        u32 Ah[4], Al[4];
        Ah[0] = xhi[(wr + gid    ) * 100 + pb + tig];
        Ah[1] = xhi[(wr + gid + 8) * 100 + pb + tig];
        Ah[2] = xhi[(wr + gid    ) * 100 + pb + tig + 4];
        Ah[3] = xhi[(wr + gid + 8) * 100 + pb + tig + 4];
        Al[0] = xlo[(wr + gid    ) * 100 + pb + tig];
        Al[1] = xlo[(wr + gid + 8) * 100 + pb + tig];
        Al[2] = xlo[(wr + gid    ) * 100 + pb + tig + 4];
        Al[3] = xlo[(wr + gid + 8) * 100 + pb + tig + 4];
        #pragma unroll
        for (int nt = 0; nt < 4; nt++) {
            const int n = nt * 8 + gid;
            u32 Bh[2] = { khi[n * 100 + pb + tig], khi[n * 100 + pb + tig + 4] };
            u32 Bl[2] = { klo[n * 100 + pb + tig], klo[n * 100 + pb + tig + 4] };
            mma16816(c[nt], Ah, Bh);
            mma16816(c[nt], Ah, Bl);
            mma16816(c[nt], Al, Bh);
        }
    }

    float m0 = -1e30f, m1 = -1e30f;
    #pragma unroll
    for (int nt = 0; nt < 4; nt++) {
        m0 = fmaxf(m0, fmaxf(c[nt][0], c[nt][1]));
        m1 = fmaxf(m1, fmaxf(c[nt][2], c[nt][3]));
    }
    m0 = fmaxf(m0, __shfl_xor_sync(0xffffffffu, m0, 1));
    m0 = fmaxf(m0, __shfl_xor_sync(0xffffffffu, m0, 2));
    m1 = fmaxf(m1, __shfl_xor_sync(0xffffffffu, m1, 1));
    m1 = fmaxf(m1, __shfl_xor_sync(0xffffffffu, m1, 2));

    float e[4][4];
    float s0 = 0.f, s1 = 0.f;
    #pragma unroll
    for (int nt = 0; nt < 4; nt++) {
        e[nt][0] = __expf(c[nt][0] - m0);
        e[nt][1] = __expf(c[nt][1] - m0);
        e[nt][2] = __expf(c[nt][2] - m1);
        e[nt][3] = __expf(c[nt][3] - m1);
        s0 += e[nt][0] + e[nt][1];
        s1 += e[nt][2] + e[nt][3];
    }
    s0 += __shfl_xor_sync(0xffffffffu, s0, 1);
    s0 += __shfl_xor_sync(0xffffffffu, s0, 2);
    s1 += __shfl_xor_sync(0xffffffffu, s1, 1);
    s1 += __shfl_xor_sync(0xffffffffu, s1, 2);
    float i0 = 1.0f / s0, i1 = 1.0f / s1;

    #pragma unroll
    for (int nt = 0; nt < 4; nt++) {
        const int n = nt * 8 + tig * 2;
        *(float2*)&w_out[(size_t)(row0 + wr + gid    ) * NS + n] =
            make_float2(e[nt][0] * i0, e[nt][1] * i0);
        *(float2*)&w_out[(size_t)(row0 + wr + gid + 8) * NS + n] =
            make_float2(e[nt][2] * i1, e[nt][3] * i1);
    }
}

// ---------------------------------------------------------------------------
// C2 (tensor core): s = w @ sl, bf16 3-term split, 2x A-reuse.
// Block = 128 rows x 128 d, 256 thr; warp = 32 rows x 64 d (two 16-row
// A-tiles share every B fragment -> B LDS per output row halved).
// 4 independent mma chains per nt (2 tiles x {hh depth-2, hl+lh depth-4}).
// Dynamic smem 40KB: slT_hi/lo [128][20], whi/wlo [128][20].
// ---------------------------------------------------------------------------
#define C2_SMEM 40960
__global__ __launch_bounds__(256, 3) void c2_kernel(const float* __restrict__ sl,
                                                    const float* __restrict__ w_in,
                                                    float* __restrict__ s_out) {
    extern __shared__ u32 c2sm[];
    u32* slT_hi = c2sm;              // [128][20]
    u32* slT_lo = c2sm + 2560;       // [128][20]
    u32* whi    = c2sm + 5120;       // [128][20]
    u32* wlo    = c2sm + 7680;       // [128][20]

    const int d0   = blockIdx.x * 128;
    const int row0 = blockIdx.y * 128;
    const int b    = row0 >> 13;
    const int tid  = threadIdx.x;

    #pragma unroll
    for (int t = 0; t < 8; t++) {    // sl split: 16 s-pairs x 128 d
        int idx = t * 256 + tid;
        int q = idx >> 7, d = idx & 127;
        const float* base = &sl[(size_t)(b * NS + 2 * q) * SD + d0 + d];
        float v0 = base[0], v1 = base[SD];
        float h0 = bf16rt(v0), h1 = bf16rt(v1);
        slT_hi[d * 20 + q] = packbf2(h0, h1);
        slT_lo[d * 20 + q] = packbf2(v0 - h0, v1 - h1);
    }
    #pragma unroll
    for (int t = 0; t < 8; t++) {    // w split: 128 rows x 16 s-pairs
        int idx = t * 256 + tid;
        int r = idx >> 4, q = idx & 15;
        const float* wb = &w_in[(size_t)(row0 + r) * NS + 2 * q];
        float v0 = wb[0], v1 = wb[1];
        float h0 = bf16rt(v0), h1 = bf16rt(v1);
        whi[r * 20 + q] = packbf2(h0, h1);
        wlo[r * 20 + q] = packbf2(v0 - h0, v1 - h1);
    }
    __syncthreads();

    const int warp = tid >> 5, lane = tid & 31;
    const int gid = lane >> 2, tig = lane & 3;
    const int wr = (warp >> 1) * 32;    // 0,32,64,96
    const int wd = (warp & 1) * 64;     // 0,64

    u32 Ah0[8], Al0[8], Ah1[8], Al1[8];
    #pragma unroll
    for (int k = 0; k < 2; k++) {
        int pb = k * 8;
        int r0a = wr + gid, r0b = wr + gid + 8;
        int r1a = r0a + 16, r1b = r0b + 16;
        Ah0[k*4+0] = whi[r0a * 20 + pb + tig];
        Ah0[k*4+1] = whi[r0b * 20 + pb + tig];
        Ah0[k*4+2] = whi[r0a * 20 + pb + tig + 4];
        Ah0[k*4+3] = whi[r0b * 20 + pb + tig + 4];
        Al0[k*4+0] = wlo[r0a * 20 + pb + tig];
        Al0[k*4+1] = wlo[r0b * 20 + pb + tig];
        Al0[k*4+2] = wlo[r0a * 20 + pb + tig + 4];
        Al0[k*4+3] = wlo[r0b * 20 + pb + tig + 4];
        Ah1[k*4+0] = whi[r1a * 20 + pb + tig];
        Ah1[k*4+1] = whi[r1b * 20 + pb + tig];
        Ah1[k*4+2] = whi[r1a * 20 + pb + tig + 4];
        Ah1[k*4+3] = whi[r1b * 20 + pb + tig + 4];
        Al1[k*4+0] = wlo[r1a * 20 + pb + tig];
        Al1[k*4+1] = wlo[r1b * 20 + pb + tig];
        Al1[k*4+2] = wlo[r1a * 20 + pb + tig + 4];
        Al1[k*4+3] = wlo[r1b * 20 + pb + tig + 4];
    }

    #pragma unroll
    for (int nt = 0; nt < 8; nt++) {
        const int dcol = wd + nt * 8 + gid;
        u32 Bh[4], Bl[4];
        Bh[0] = slT_hi[dcol * 20 + tig];      Bh[1] = slT_hi[dcol * 20 + tig + 4];
        Bh[2] = slT_hi[dcol * 20 + 8 + tig];  Bh[3] = slT_hi[dcol * 20 + 12 + tig];
        Bl[0] = slT_lo[dcol * 20 + tig];      Bl[1] = slT_lo[dcol * 20 + tig + 4];
        Bl[2] = slT_lo[dcol * 20 + 8 + tig];  Bl[3] = slT_lo[dcol * 20 + 12 + tig];

        // 4 independent chains: tile0/tile1 x {hh (depth 2), hl+lh (depth 4)}
        float c0h[4] = {0.f, 0.f, 0.f, 0.f};
        float c0x[4] = {0.f, 0.f, 0.f, 0.f};
        float c1h[4] = {0.f, 0.f, 0.f, 0.f};
        float c1x[4] = {0.f, 0.f, 0.f, 0.f};
        mma16816(c0h, &Ah0[0], &Bh[0]);
        mma16816(c1h, &Ah1[0], &Bh[0]);
        mma16816(c0x, &Ah0[0], &Bl[0]);
        mma16816(c1x, &Ah1[0], &Bl[0]);
        mma16816(c0h, &Ah0[4], &Bh[2]);
        mma16816(c1h, &Ah1[4], &Bh[2]);
        mma16816(c0x, &Al0[0], &Bh[0]);
        mma16816(c1x, &Al1[0], &Bh[0]);
        mma16816(c0x, &Ah0[4], &Bl[2]);
        mma16816(c1x, &Ah1[4], &Bl[2]);
        mma16816(c0x, &Al0[4], &Bh[2]);
        mma16816(c1x, &Al1[4], &Bh[2]);

        const int dg = d0 + wd + nt * 8 + tig * 2;
        *(float2*)&s_out[(size_t)(row0 + wr + gid         ) * SD + dg] =
            make_float2(c0h[0] + c0x[0], c0h[1] + c0x[1]);
        *(float2*)&s_out[(size_t)(row0 + wr + gid + 8     ) * SD + dg] =
            make_float2(c0h[2] + c0x[2], c0h[3] + c0x[3]);
        *(float2*)&s_out[(size_t)(row0 + wr + gid + 16    ) * SD + dg] =
            make_float2(c1h[0] + c1x[0], c1h[1] + c1x[1]);
        *(float2*)&s_out[(size_t)(row0 + wr + gid + 24    ) * SD + dg] =
            make_float2(c1h[2] + c1x[2], c1h[3] + c1x[3]);
    }
}

// ---------------------------------------------------------------------------
extern "C" void kernel_launch(void* const* d_in, const int* in_sizes, int n_in,
                              void* d_out, int out_size) {
    const float* x  = (const float*)d_in[0];   // [4,8192,180]
    const float* sl = (const float*)d_in[1];   // [4,32,1536]
    const float* Wq = (const float*)d_in[2];   // [180,1536]
    const float* Wk = (const float*)d_in[3];   // [1536,1536]
    float* out   = (float*)d_out;
    float* s_out = out;                               // [4,8192,1536]
    float* w_out = out + (size_t)NB * NR * SD;        // [4,8192,32]

    static int attr_done = 0;
    if (!attr_done) {
        cudaFuncSetAttribute(c1_kernel,
                             cudaFuncAttributeMaxDynamicSharedMemorySize, C1_SMEM);
        cudaFuncSetAttribute(c2_kernel,
                             cudaFuncAttributeMaxDynamicSharedMemorySize, C2_SMEM);
        attr_done = 1;
    }

    p1_kernel<<<dim3(AD / 256, BS / 32, KS), 128>>>(sl, Wk);
    p1r_kernel<<<(BS * AD / 4) / 256, 256>>>();
    p2_kernel<<<dim3(192 / JT, AC), 256>>>(Wq);
    c1_kernel<<<(NB * NR) / 64, 128, C1_SMEM>>>(x, w_out);
    c2_kernel<<<dim3(SD / 128, (NB * NR) / 128), 256, C2_SMEM>>>(sl, w_out, s_out);
}

// round 15
// speedup vs baseline: 1.3200x; 1.0628x over previous
#include <cuda_runtime.h>
#include <cuda_bf16.h>

// ---------------------------------------------------------------------------
// MixingBlock: s = softmax((x Wq)(sl Wk)^T * scale) @ sl,  w = the softmax
// Restructure: dots = x @ KQ^T with KQ = scale * (sl Wk) Wq^T  (tiny [128,180])
// Pipeline: p1 -> p1r (reduce + zero KQT) -> p2 (atomic KQ) -> c1 -> c2
// ---------------------------------------------------------------------------

#define NB 4
#define NR 8192
#define NS 32
#define IN_DIM 180
#define SD 1536
#define AD 1536
#define BS (NB*NS)          // 128
#define KS 16               // d-split for p1
#define KCHUNK (SD/KS)      // 96
#define AC 24               // a-chunks for p2
#define ACHUNK (AD/AC)      // 64
#define JT 16               // j-tile for p2

typedef unsigned long long ull;
typedef unsigned int u32;

__device__ float g_kpart[KS][BS][AD];     // p1 partials
__device__ float g_kred[BS][AD];          // reduced k
__device__ float g_KQT[IN_DIM][BS];       // KQ transposed (scale folded in)

// ---- packed f32x2 helpers -------------------------------------------------
__device__ __forceinline__ ull fpack(float x, float y) {
    ull r; asm("mov.b64 %0, {%1, %2};" : "=l"(r) : "f"(x), "f"(y)); return r;
}
__device__ __forceinline__ float2 funpack(ull v) {
    float2 r; asm("mov.b64 {%0, %1}, %2;" : "=f"(r.x), "=f"(r.y) : "l"(v)); return r;
}
__device__ __forceinline__ ull ffma2(ull a, ull b, ull c) {
    ull d; asm("fma.rn.f32x2 %0, %1, %2, %3;" : "=l"(d) : "l"(a), "l"(b), "l"(c)); return d;
}
__device__ __forceinline__ ull d2u(double d) { return __double_as_longlong(d); }
__device__ __forceinline__ double u2d(ull v) { return __longlong_as_double(v); }

// ---- bf16 helpers ---------------------------------------------------------
__device__ __forceinline__ u32 packbf2(float x, float y) {
    __nv_bfloat162 t = __floats2bfloat162_rn(x, y);
    return *reinterpret_cast<u32*>(&t);
}
__device__ __forceinline__ float bf16rt(float v) {
    return __bfloat162float(__float2bfloat16_rn(v));
}
__device__ __forceinline__ void mma16816(float c[4], const u32 a[4], const u32 b[2]) {
    asm volatile(
        "mma.sync.aligned.m16n8k16.row.col.f32.bf16.bf16.f32 "
        "{%0,%1,%2,%3},{%4,%5,%6,%7},{%8,%9},{%0,%1,%2,%3};"
        : "+f"(c[0]), "+f"(c[1]), "+f"(c[2]), "+f"(c[3])
        : "r"(a[0]), "r"(a[1]), "r"(a[2]), "r"(a[3]), "r"(b[0]), "r"(b[1]));
}

// ---------------------------------------------------------------------------
// P1: g_kpart[p][m][n] = sum_{d in chunk p} sl[m][d] * Wk[d][n]
// ---------------------------------------------------------------------------
__global__ __launch_bounds__(128) void p1_kernel(const float* __restrict__ sl,
                                                 const float* __restrict__ Wk) {
    const int n0 = blockIdx.x * 256;
    const int m0 = blockIdx.y * 32;
    const int p  = blockIdx.z;
    const int d0 = p * KCHUNK;
    __shared__ float sWk[16][256];
    __shared__ ull   sslp[16][33];
    const int tid  = threadIdx.x;
    const int warp = tid >> 5, lane = tid & 31;
    const int mbase = warp * 8;

    ull acc[8][4];
    #pragma unroll
    for (int i = 0; i < 8; i++)
        #pragma unroll
        for (int q = 0; q < 4; q++) acc[i][q] = 0ULL;

    for (int kk = 0; kk < KCHUNK; kk += 16) {
        __syncthreads();
        #pragma unroll
        for (int t = 0; t < 8; t++) {
            int idx = t * 128 + tid;
            int dd = idx >> 6, nq = idx & 63;
            *(float4*)&sWk[dd][nq * 4] =
                *(const float4*)&Wk[(size_t)(d0 + kk + dd) * AD + n0 + nq * 4];
        }
        #pragma unroll
        for (int t = 0; t < 4; t++) {
            int idx = t * 128 + tid;
            int m = idx >> 4, dd = idx & 15;
            float v = sl[(size_t)(m0 + m) * SD + d0 + kk + dd];
            sslp[dd][m] = fpack(v, v);
        }
        __syncthreads();
        #pragma unroll
        for (int dd = 0; dd < 16; dd++) {
            double2 a01 = *(const double2*)&sWk[dd][lane * 4];
            double2 a23 = *(const double2*)&sWk[dd][128 + lane * 4];
            ull A0 = d2u(a01.x), A1 = d2u(a01.y), A2 = d2u(a23.x), A3 = d2u(a23.y);
            #pragma unroll
            for (int i = 0; i < 8; i++) {
                ull wv = sslp[dd][mbase + i];
                acc[i][0] = ffma2(A0, wv, acc[i][0]);
                acc[i][1] = ffma2(A1, wv, acc[i][1]);
                acc[i][2] = ffma2(A2, wv, acc[i][2]);
                acc[i][3] = ffma2(A3, wv, acc[i][3]);
            }
        }
    }
    #pragma unroll
    for (int i = 0; i < 8; i++) {
        int m = m0 + mbase + i;
        float* dst = &g_kpart[p][m][n0 + lane * 4];
        *(double2*)dst         = make_double2(u2d(acc[i][0]), u2d(acc[i][1]));
        *(double2*)(dst + 128) = make_double2(u2d(acc[i][2]), u2d(acc[i][3]));
    }
}

// ---------------------------------------------------------------------------
// P1R: g_kred = sum_p g_kpart[p]; also zeros g_KQT for p2's atomics.
// ---------------------------------------------------------------------------
__global__ __launch_bounds__(256) void p1r_kernel() {
    int gid = blockIdx.x * 256 + threadIdx.x;
    if (gid < IN_DIM * BS) (&g_KQT[0][0])[gid] = 0.f;
    const float4* src = (const float4*)&g_kpart[0][0][0];
    float4* dst = (float4*)&g_kred[0][0];
    const int stride = (BS * AD) / 4;
    float4 a = make_float4(0.f, 0.f, 0.f, 0.f);
    #pragma unroll
    for (int p = 0; p < KS; p++) {
        float4 v = src[(size_t)p * stride + gid];
        a.x += v.x; a.y += v.y; a.z += v.z; a.w += v.w;
    }
    dst[gid] = a;
}

// ---------------------------------------------------------------------------
// P2: g_KQT[j][m] += scale * sum_{a in chunk} kred[m][a] * Wq[j][a]
// ---------------------------------------------------------------------------
__global__ __launch_bounds__(256) void p2_kernel(const float* __restrict__ Wq) {
    const int j0 = blockIdx.x * JT;
    const int ac = blockIdx.y;
    const int a0 = ac * ACHUNK;
    __shared__ float ksm[64][130];
    __shared__ ull   wqs[64][18];
    const int tid = threadIdx.x;
    const int mp = tid & 63;
    const int jg = tid >> 6;

    #pragma unroll
    for (int t = 0; t < 8; t++) {
        int idx = t * 256 + tid;
        int m = idx >> 4, aq = idx & 15;
        float4 v = *(const float4*)&g_kred[m][a0 + aq * 4];
        ksm[aq * 4 + 0][m] = v.x;
        ksm[aq * 4 + 1][m] = v.y;
        ksm[aq * 4 + 2][m] = v.z;
        ksm[aq * 4 + 3][m] = v.w;
    }
    const float scale = rsqrtf((float)AD);
    #pragma unroll
    for (int t = 0; t < 4; t++) {
        int idx = t * 256 + tid;
        int jj = idx >> 6, a = idx & 63;
        int j = j0 + jj;
        float v = (j < IN_DIM) ? Wq[(size_t)j * AD + a0 + a] * scale : 0.f;
        wqs[a][jj] = fpack(v, v);
    }
    __syncthreads();

    ull acc[4] = {0ULL, 0ULL, 0ULL, 0ULL};
    #pragma unroll 4
    for (int a = 0; a < ACHUNK; a++) {
        ull kp = *(const ull*)&ksm[a][2 * mp];
        double2 w01 = *(const double2*)&wqs[a][jg * 4];
        double2 w23 = *(const double2*)&wqs[a][jg * 4 + 2];
        acc[0] = ffma2(kp, d2u(w01.x), acc[0]);
        acc[1] = ffma2(kp, d2u(w01.y), acc[1]);
        acc[2] = ffma2(kp, d2u(w23.x), acc[2]);
        acc[3] = ffma2(kp, d2u(w23.y), acc[3]);
    }
    #pragma unroll
    for (int q = 0; q < 4; q++) {
        int j = j0 + jg * 4 + q;
        if (j < IN_DIM) {
            float2 v = funpack(acc[q]);
            atomicAdd(&g_KQT[j][2 * mp], v.x);
            atomicAdd(&g_KQT[j][2 * mp + 1], v.y);
        }
    }
}

// ---------------------------------------------------------------------------
// C1 (tensor core): dots = x @ KQ (K=180 pad 192), softmax, write w.
// NEW: x A-fragments loaded DIRECTLY from global (sector-coalesced float2),
// hi/lo split in registers. smem = khi/klo only (25.6KB static) -> ~24 warps/SM.
// Block = 64 rows, 128 thr (4 warps), warp = 16 rows x 32 slots.
// ---------------------------------------------------------------------------
__global__ __launch_bounds__(128, 6) void c1_kernel(const float* __restrict__ x,
                                                    float* __restrict__ w_out) {
    __shared__ u32 khi[NS * 100];
    __shared__ u32 klo[NS * 100];

    const int row0 = blockIdx.x * 64;
    const int b = row0 >> 13;
    const int tid = threadIdx.x;

    // fill KQ: [s][jp] from g_KQT[j][b*32+s], zero-padded to 96 pairs
    for (int idx = tid; idx < NS * 96; idx += 128) {
        int s = idx & 31, jp = idx >> 5;
        float f0 = (2 * jp     < IN_DIM) ? g_KQT[2 * jp][b * NS + s]     : 0.f;
        float f1 = (2 * jp + 1 < IN_DIM) ? g_KQT[2 * jp + 1][b * NS + s] : 0.f;
        float h0 = bf16rt(f0), h1 = bf16rt(f1);
        khi[s * 100 + jp] = packbf2(h0, h1);
        klo[s * 100 + jp] = packbf2(f0 - h0, f1 - h1);
    }
    __syncthreads();

    const int warp = tid >> 5, lane = tid & 31;
    const int gid = lane >> 2, tig = lane & 3;
    const int wr = warp * 16;
    const float* xr0 = x + (size_t)(row0 + wr + gid) * IN_DIM;
    const float* xr1 = xr0 + 8 * IN_DIM;

    float c[4][4];
    #pragma unroll
    for (int nt = 0; nt < 4; nt++)
        #pragma unroll
        for (int q = 0; q < 4; q++) c[nt][q] = 0.f;

    const float2 z2 = make_float2(0.f, 0.f);
    #pragma unroll
    for (int kt = 0; kt < 12; kt++) {
        const int kb = kt * 16;
        const int k0 = kb + 2 * tig;
        const int k1 = kb + 8 + 2 * tig;
        float2 a00 = (k0 < 179) ? *(const float2*)(xr0 + k0) : z2;
        float2 a01 = (k1 < 179) ? *(const float2*)(xr0 + k1) : z2;
        float2 a10 = (k0 < 179) ? *(const float2*)(xr1 + k0) : z2;
        float2 a11 = (k1 < 179) ? *(const float2*)(xr1 + k1) : z2;

        u32 Ah[4], Al[4];
        {
            float hx = bf16rt(a00.x), hy = bf16rt(a00.y);
            Ah[0] = packbf2(hx, hy); Al[0] = packbf2(a00.x - hx, a00.y - hy);
        }
        {
            float hx = bf16rt(a10.x), hy = bf16rt(a10.y);
            Ah[1] = packbf2(hx, hy); Al[1] = packbf2(a10.x - hx, a10.y - hy);
        }
        {
            float hx = bf16rt(a01.x), hy = bf16rt(a01.y);
            Ah[2] = packbf2(hx, hy); Al[2] = packbf2(a01.x - hx, a01.y - hy);
        }
        {
            float hx = bf16rt(a11.x), hy = bf16rt(a11.y);
            Ah[3] = packbf2(hx, hy); Al[3] = packbf2(a11.x - hx, a11.y - hy);
        }

        const int pb = kt * 8;
        #pragma unroll
        for (int nt = 0; nt < 4; nt++) {
            const int n = nt * 8 + gid;
            u32 Bh[2] = { khi[n * 100 + pb + tig], khi[n * 100 + pb + tig + 4] };
            u32 Bl[2] = { klo[n * 100 + pb + tig], klo[n * 100 + pb + tig + 4] };
            mma16816(c[nt], Ah, Bh);
            mma16816(c[nt], Ah, Bl);
            mma16816(c[nt], Al, Bh);
        }
    }

    float m0 = -1e30f, m1 = -1e30f;
    #pragma unroll
    for (int nt = 0; nt < 4; nt++) {
        m0 = fmaxf(m0, fmaxf(c[nt][0], c[nt][1]));
        m1 = fmaxf(m1, fmaxf(c[nt][2], c[nt][3]));
    }
    m0 = fmaxf(m0, __shfl_xor_sync(0xffffffffu, m0, 1));
    m0 = fmaxf(m0, __shfl_xor_sync(0xffffffffu, m0, 2));
    m1 = fmaxf(m1, __shfl_xor_sync(0xffffffffu, m1, 1));
    m1 = fmaxf(m1, __shfl_xor_sync(0xffffffffu, m1, 2));

    float e[4][4];
    float s0 = 0.f, s1 = 0.f;
    #pragma unroll
    for (int nt = 0; nt < 4; nt++) {
        e[nt][0] = __expf(c[nt][0] - m0);
        e[nt][1] = __expf(c[nt][1] - m0);
        e[nt][2] = __expf(c[nt][2] - m1);
        e[nt][3] = __expf(c[nt][3] - m1);
        s0 += e[nt][0] + e[nt][1];
        s1 += e[nt][2] + e[nt][3];
    }
    s0 += __shfl_xor_sync(0xffffffffu, s0, 1);
    s0 += __shfl_xor_sync(0xffffffffu, s0, 2);
    s1 += __shfl_xor_sync(0xffffffffu, s1, 1);
    s1 += __shfl_xor_sync(0xffffffffu, s1, 2);
    float i0 = 1.0f / s0, i1 = 1.0f / s1;

    #pragma unroll
    for (int nt = 0; nt < 4; nt++) {
        const int n = nt * 8 + tig * 2;
        *(float2*)&w_out[(size_t)(row0 + wr + gid    ) * NS + n] =
            make_float2(e[nt][0] * i0, e[nt][1] * i0);
        *(float2*)&w_out[(size_t)(row0 + wr + gid + 8) * NS + n] =
            make_float2(e[nt][2] * i1, e[nt][3] * i1);
    }
}

// ---------------------------------------------------------------------------
// C2 (tensor core): s = w @ sl, bf16 3-term split, 2x A-reuse.
// (unchanged from the 111.1us run)
// ---------------------------------------------------------------------------
#define C2_SMEM 40960
__global__ __launch_bounds__(256, 3) void c2_kernel(const float* __restrict__ sl,
                                                    const float* __restrict__ w_in,
                                                    float* __restrict__ s_out) {
    extern __shared__ u32 c2sm[];
    u32* slT_hi = c2sm;              // [128][20]
    u32* slT_lo = c2sm + 2560;       // [128][20]
    u32* whi    = c2sm + 5120;       // [128][20]
    u32* wlo    = c2sm + 7680;       // [128][20]

    const int d0   = blockIdx.x * 128;
    const int row0 = blockIdx.y * 128;
    const int b    = row0 >> 13;
    const int tid  = threadIdx.x;

    #pragma unroll
    for (int t = 0; t < 8; t++) {
        int idx = t * 256 + tid;
        int q = idx >> 7, d = idx & 127;
        const float* base = &sl[(size_t)(b * NS + 2 * q) * SD + d0 + d];
        float v0 = base[0], v1 = base[SD];
        float h0 = bf16rt(v0), h1 = bf16rt(v1);
        slT_hi[d * 20 + q] = packbf2(h0, h1);
        slT_lo[d * 20 + q] = packbf2(v0 - h0, v1 - h1);
    }
    #pragma unroll
    for (int t = 0; t < 8; t++) {
        int idx = t * 256 + tid;
        int r = idx >> 4, q = idx & 15;
        const float* wb = &w_in[(size_t)(row0 + r) * NS + 2 * q];
        float v0 = wb[0], v1 = wb[1];
        float h0 = bf16rt(v0), h1 = bf16rt(v1);
        whi[r * 20 + q] = packbf2(h0, h1);
        wlo[r * 20 + q] = packbf2(v0 - h0, v1 - h1);
    }
    __syncthreads();

    const int warp = tid >> 5, lane = tid & 31;
    const int gid = lane >> 2, tig = lane & 3;
    const int wr = (warp >> 1) * 32;    // 0,32,64,96
    const int wd = (warp & 1) * 64;     // 0,64

    u32 Ah0[8], Al0[8], Ah1[8], Al1[8];
    #pragma unroll
    for (int k = 0; k < 2; k++) {
        int pb = k * 8;
        int r0a = wr + gid, r0b = wr + gid + 8;
        int r1a = r0a + 16, r1b = r0b + 16;
        Ah0[k*4+0] = whi[r0a * 20 + pb + tig];
        Ah0[k*4+1] = whi[r0b * 20 + pb + tig];
        Ah0[k*4+2] = whi[r0a * 20 + pb + tig + 4];
        Ah0[k*4+3] = whi[r0b * 20 + pb + tig + 4];
        Al0[k*4+0] = wlo[r0a * 20 + pb + tig];
        Al0[k*4+1] = wlo[r0b * 20 + pb + tig];
        Al0[k*4+2] = wlo[r0a * 20 + pb + tig + 4];
        Al0[k*4+3] = wlo[r0b * 20 + pb + tig + 4];
        Ah1[k*4+0] = whi[r1a * 20 + pb + tig];
        Ah1[k*4+1] = whi[r1b * 20 + pb + tig];
        Ah1[k*4+2] = whi[r1a * 20 + pb + tig + 4];
        Ah1[k*4+3] = whi[r1b * 20 + pb + tig + 4];
        Al1[k*4+0] = wlo[r1a * 20 + pb + tig];
        Al1[k*4+1] = wlo[r1b * 20 + pb + tig];
        Al1[k*4+2] = wlo[r1a * 20 + pb + tig + 4];
        Al1[k*4+3] = wlo[r1b * 20 + pb + tig + 4];
    }

    #pragma unroll
    for (int nt = 0; nt < 8; nt++) {
        const int dcol = wd + nt * 8 + gid;
        u32 Bh[4], Bl[4];
        Bh[0] = slT_hi[dcol * 20 + tig];      Bh[1] = slT_hi[dcol * 20 + tig + 4];
        Bh[2] = slT_hi[dcol * 20 + 8 + tig];  Bh[3] = slT_hi[dcol * 20 + 12 + tig];
        Bl[0] = slT_lo[dcol * 20 + tig];      Bl[1] = slT_lo[dcol * 20 + tig + 4];
        Bl[2] = slT_lo[dcol * 20 + 8 + tig];  Bl[3] = slT_lo[dcol * 20 + 12 + tig];

        float c0h[4] = {0.f, 0.f, 0.f, 0.f};
        float c0x[4] = {0.f, 0.f, 0.f, 0.f};
        float c1h[4] = {0.f, 0.f, 0.f, 0.f};
        float c1x[4] = {0.f, 0.f, 0.f, 0.f};
        mma16816(c0h, &Ah0[0], &Bh[0]);
        mma16816(c1h, &Ah1[0], &Bh[0]);
        mma16816(c0x, &Ah0[0], &Bl[0]);
        mma16816(c1x, &Ah1[0], &Bl[0]);
        mma16816(c0h, &Ah0[4], &Bh[2]);
        mma16816(c1h, &Ah1[4], &Bh[2]);
        mma16816(c0x, &Al0[0], &Bh[0]);
        mma16816(c1x, &Al1[0], &Bh[0]);
        mma16816(c0x, &Ah0[4], &Bl[2]);
        mma16816(c1x, &Ah1[4], &Bl[2]);
        mma16816(c0x, &Al0[4], &Bh[2]);
        mma16816(c1x, &Al1[4], &Bh[2]);

        const int dg = d0 + wd + nt * 8 + tig * 2;
        *(float2*)&s_out[(size_t)(row0 + wr + gid         ) * SD + dg] =
            make_float2(c0h[0] + c0x[0], c0h[1] + c0x[1]);
        *(float2*)&s_out[(size_t)(row0 + wr + gid + 8     ) * SD + dg] =
            make_float2(c0h[2] + c0x[2], c0h[3] + c0x[3]);
        *(float2*)&s_out[(size_t)(row0 + wr + gid + 16    ) * SD + dg] =
            make_float2(c1h[0] + c1x[0], c1h[1] + c1x[1]);
        *(float2*)&s_out[(size_t)(row0 + wr + gid + 24    ) * SD + dg] =
            make_float2(c1h[2] + c1x[2], c1h[3] + c1x[3]);
    }
}

// ---------------------------------------------------------------------------
extern "C" void kernel_launch(void* const* d_in, const int* in_sizes, int n_in,
                              void* d_out, int out_size) {
    const float* x  = (const float*)d_in[0];   // [4,8192,180]
    const float* sl = (const float*)d_in[1];   // [4,32,1536]
    const float* Wq = (const float*)d_in[2];   // [180,1536]
    const float* Wk = (const float*)d_in[3];   // [1536,1536]
    float* out   = (float*)d_out;
    float* s_out = out;                               // [4,8192,1536]
    float* w_out = out + (size_t)NB * NR * SD;        // [4,8192,32]

    static int attr_done = 0;
    if (!attr_done) {
        cudaFuncSetAttribute(c2_kernel,
                             cudaFuncAttributeMaxDynamicSharedMemorySize, C2_SMEM);
        attr_done = 1;
    }

    p1_kernel<<<dim3(AD / 256, BS / 32, KS), 128>>>(sl, Wk);
    p1r_kernel<<<(BS * AD / 4) / 256, 256>>>();
    p2_kernel<<<dim3(192 / JT, AC), 256>>>(Wq);
    c1_kernel<<<(NB * NR) / 64, 128>>>(x, w_out);
    c2_kernel<<<dim3(SD / 128, (NB * NR) / 128), 256, C2_SMEM>>>(sl, w_out, s_out);
}

// round 16
// speedup vs baseline: 1.3960x; 1.0576x over previous
#include <cuda_runtime.h>
#include <cuda_bf16.h>

// ---------------------------------------------------------------------------
// MixingBlock: s = softmax((x Wq)(sl Wk)^T * scale) @ sl,  w = the softmax
// Restructure: dots = x @ KQ^T with KQ = scale * (sl Wk) Wq^T  (tiny [128,180])
// Pipeline: p1m (bf16 mma GEMM, partials) -> p1r (reduce + zero KQT)
//           -> p2 (atomic KQ) -> c1 (bf16 mma) -> c2 (bf16 mma)
// ---------------------------------------------------------------------------

#define NB 4
#define NR 8192
#define NS 32
#define IN_DIM 180
#define SD 1536
#define AD 1536
#define BS (NB*NS)          // 128
#define P1KC 6              // k-chunks for p1m
#define P1KCHUNK (SD/P1KC)  // 256
#define AC 24               // a-chunks for p2
#define ACHUNK (AD/AC)      // 64
#define JT 16               // j-tile for p2

typedef unsigned long long ull;
typedef unsigned int u32;

__device__ float g_kp2[P1KC][BS][AD];     // p1m partials (4.7 MB)
__device__ float g_kred[BS][AD];          // reduced k
__device__ float g_KQT[IN_DIM][BS];       // KQ transposed (scale folded in)

// ---- packed f32x2 helpers -------------------------------------------------
__device__ __forceinline__ ull fpack(float x, float y) {
    ull r; asm("mov.b64 %0, {%1, %2};" : "=l"(r) : "f"(x), "f"(y)); return r;
}
__device__ __forceinline__ float2 funpack(ull v) {
    float2 r; asm("mov.b64 {%0, %1}, %2;" : "=f"(r.x), "=f"(r.y) : "l"(v)); return r;
}
__device__ __forceinline__ ull ffma2(ull a, ull b, ull c) {
    ull d; asm("fma.rn.f32x2 %0, %1, %2, %3;" : "=l"(d) : "l"(a), "l"(b), "l"(c)); return d;
}
__device__ __forceinline__ ull d2u(double d) { return __double_as_longlong(d); }
__device__ __forceinline__ double u2d(ull v) { return __longlong_as_double(v); }

// ---- bf16 helpers ---------------------------------------------------------
__device__ __forceinline__ u32 packbf2(float x, float y) {
    __nv_bfloat162 t = __floats2bfloat162_rn(x, y);
    return *reinterpret_cast<u32*>(&t);
}
__device__ __forceinline__ float bf16rt(float v) {
    return __bfloat162float(__float2bfloat16_rn(v));
}
__device__ __forceinline__ void mma16816(float c[4], const u32 a[4], const u32 b[2]) {
    asm volatile(
        "mma.sync.aligned.m16n8k16.row.col.f32.bf16.bf16.f32 "
        "{%0,%1,%2,%3},{%4,%5,%6,%7},{%8,%9},{%0,%1,%2,%3};"
        : "+f"(c[0]), "+f"(c[1]), "+f"(c[2]), "+f"(c[3])
        : "r"(a[0]), "r"(a[1]), "r"(a[2]), "r"(a[3]), "r"(b[0]), "r"(b[1]));
}

// ---------------------------------------------------------------------------
// P1M (tensor core): k = sl @ Wk  (M=128, N=1536, K=1536), bf16 3-term split.
// grid (24 n-tiles of 64, 6 k-chunks of 256), 256 thr (8 warps).
// Warp = 16 m x 64 n (8 n-tiles). Sub-chunks of 64 k staged in smem
// (stride-33 padding -> conflict-free fragment loads).
// smem: sAh/sAl [128][33], sBh/sBl [64][33] = 50.7 KB dynamic.
// Writes fp32 partials g_kp2[kc].
// ---------------------------------------------------------------------------
#define P1_SMEM ((128*33*2 + 64*33*2) * 4)
__global__ __launch_bounds__(256, 2) void p1m_kernel(const float* __restrict__ sl,
                                                     const float* __restrict__ Wk) {
    extern __shared__ u32 p1sm[];
    u32* sAh = p1sm;                   // [128][33]
    u32* sAl = p1sm + 128 * 33;
    u32* sBh = p1sm + 2 * 128 * 33;    // [64][33]
    u32* sBl = p1sm + 2 * 128 * 33 + 64 * 33;

    const int n0  = blockIdx.x * 64;
    const int kc  = blockIdx.y;
    const int kc0 = kc * P1KCHUNK;
    const int tid = threadIdx.x;
    const int warp = tid >> 5, lane = tid & 31;
    const int gid = lane >> 2, tig = lane & 3;
    const int mw = warp * 16;

    float c[8][4];
    #pragma unroll
    for (int nt = 0; nt < 8; nt++)
        #pragma unroll
        for (int q = 0; q < 4; q++) c[nt][q] = 0.f;

    for (int sc = 0; sc < P1KCHUNK / 64; sc++) {
        const int kb = kc0 + sc * 64;
        __syncthreads();
        // fill A: 128 m x 32 k-pairs from sl (coalesced float2)
        #pragma unroll
        for (int t = 0; t < 16; t++) {
            int idx = t * 256 + tid;
            int m = idx >> 5, kp = idx & 31;
            float2 v = *(const float2*)&sl[(size_t)m * SD + kb + 2 * kp];
            float hx = bf16rt(v.x), hy = bf16rt(v.y);
            sAh[m * 33 + kp] = packbf2(hx, hy);
            sAl[m * 33 + kp] = packbf2(v.x - hx, v.y - hy);
        }
        // fill B: 64 n x 32 k-pairs, transposed from Wk[k][n] (coalesced over n)
        #pragma unroll
        for (int t = 0; t < 8; t++) {
            int idx = t * 256 + tid;
            int kp = idx >> 6, n = idx & 63;
            float v0 = Wk[(size_t)(kb + 2 * kp)     * AD + n0 + n];
            float v1 = Wk[(size_t)(kb + 2 * kp + 1) * AD + n0 + n];
            float h0 = bf16rt(v0), h1 = bf16rt(v1);
            sBh[n * 33 + kp] = packbf2(h0, h1);
            sBl[n * 33 + kp] = packbf2(v0 - h0, v1 - h1);
        }
        __syncthreads();

        #pragma unroll
        for (int ks = 0; ks < 4; ks++) {
            const int kp0 = ks * 8;
            u32 Ah[4], Al[4];
            Ah[0] = sAh[(mw + gid    ) * 33 + kp0 + tig];
            Ah[1] = sAh[(mw + gid + 8) * 33 + kp0 + tig];
            Ah[2] = sAh[(mw + gid    ) * 33 + kp0 + tig + 4];
            Ah[3] = sAh[(mw + gid + 8) * 33 + kp0 + tig + 4];
            Al[0] = sAl[(mw + gid    ) * 33 + kp0 + tig];
            Al[1] = sAl[(mw + gid + 8) * 33 + kp0 + tig];
            Al[2] = sAl[(mw + gid    ) * 33 + kp0 + tig + 4];
            Al[3] = sAl[(mw + gid + 8) * 33 + kp0 + tig + 4];
            #pragma unroll
            for (int nt = 0; nt < 8; nt++) {
                const int n = nt * 8 + gid;
                u32 Bh[2] = { sBh[n * 33 + kp0 + tig], sBh[n * 33 + kp0 + tig + 4] };
                u32 Bl[2] = { sBl[n * 33 + kp0 + tig], sBl[n * 33 + kp0 + tig + 4] };
                mma16816(c[nt], Ah, Bh);
                mma16816(c[nt], Ah, Bl);
                mma16816(c[nt], Al, Bh);
            }
        }
    }
    #pragma unroll
    for (int nt = 0; nt < 8; nt++) {
        const int dg = n0 + nt * 8 + tig * 2;
        *(float2*)&g_kp2[kc][mw + gid    ][dg] = make_float2(c[nt][0], c[nt][1]);
        *(float2*)&g_kp2[kc][mw + gid + 8][dg] = make_float2(c[nt][2], c[nt][3]);
    }
}

// ---------------------------------------------------------------------------
// P1R: g_kred = sum_kc g_kp2[kc]; also zeros g_KQT for p2's atomics.
// ---------------------------------------------------------------------------
__global__ __launch_bounds__(256) void p1r_kernel() {
    int gid = blockIdx.x * 256 + threadIdx.x;    // over 128*1536/4 = 49152
    if (gid < IN_DIM * BS) (&g_KQT[0][0])[gid] = 0.f;
    const float4* src = (const float4*)&g_kp2[0][0][0];
    float4* dst = (float4*)&g_kred[0][0];
    const int stride = (BS * AD) / 4;
    float4 a = make_float4(0.f, 0.f, 0.f, 0.f);
    #pragma unroll
    for (int p = 0; p < P1KC; p++) {
        float4 v = src[(size_t)p * stride + gid];
        a.x += v.x; a.y += v.y; a.z += v.z; a.w += v.w;
    }
    dst[gid] = a;
}

// ---------------------------------------------------------------------------
// P2: g_KQT[j][m] += scale * sum_{a in chunk} kred[m][a] * Wq[j][a]
// (unchanged, proven)
// ---------------------------------------------------------------------------
__global__ __launch_bounds__(256) void p2_kernel(const float* __restrict__ Wq) {
    const int j0 = blockIdx.x * JT;
    const int ac = blockIdx.y;
    const int a0 = ac * ACHUNK;
    __shared__ float ksm[64][130];
    __shared__ ull   wqs[64][18];
    const int tid = threadIdx.x;
    const int mp = tid & 63;
    const int jg = tid >> 6;

    #pragma unroll
    for (int t = 0; t < 8; t++) {
        int idx = t * 256 + tid;
        int m = idx >> 4, aq = idx & 15;
        float4 v = *(const float4*)&g_kred[m][a0 + aq * 4];
        ksm[aq * 4 + 0][m] = v.x;
        ksm[aq * 4 + 1][m] = v.y;
        ksm[aq * 4 + 2][m] = v.z;
        ksm[aq * 4 + 3][m] = v.w;
    }
    const float scale = rsqrtf((float)AD);
    #pragma unroll
    for (int t = 0; t < 4; t++) {
        int idx = t * 256 + tid;
        int jj = idx >> 6, a = idx & 63;
        int j = j0 + jj;
        float v = (j < IN_DIM) ? Wq[(size_t)j * AD + a0 + a] * scale : 0.f;
        wqs[a][jj] = fpack(v, v);
    }
    __syncthreads();

    ull acc[4] = {0ULL, 0ULL, 0ULL, 0ULL};
    #pragma unroll 4
    for (int a = 0; a < ACHUNK; a++) {
        ull kp = *(const ull*)&ksm[a][2 * mp];
        double2 w01 = *(const double2*)&wqs[a][jg * 4];
        double2 w23 = *(const double2*)&wqs[a][jg * 4 + 2];
        acc[0] = ffma2(kp, d2u(w01.x), acc[0]);
        acc[1] = ffma2(kp, d2u(w01.y), acc[1]);
        acc[2] = ffma2(kp, d2u(w23.x), acc[2]);
        acc[3] = ffma2(kp, d2u(w23.y), acc[3]);
    }
    #pragma unroll
    for (int q = 0; q < 4; q++) {
        int j = j0 + jg * 4 + q;
        if (j < IN_DIM) {
            float2 v = funpack(acc[q]);
            atomicAdd(&g_KQT[j][2 * mp], v.x);
            atomicAdd(&g_KQT[j][2 * mp + 1], v.y);
        }
    }
}

// ---------------------------------------------------------------------------
// C1 (tensor core): dots = x @ KQ (K=180 pad 192), softmax, write w.
// (unchanged from the 104.5us run)
// ---------------------------------------------------------------------------
__global__ __launch_bounds__(128, 6) void c1_kernel(const float* __restrict__ x,
                                                    float* __restrict__ w_out) {
    __shared__ u32 khi[NS * 100];
    __shared__ u32 klo[NS * 100];

    const int row0 = blockIdx.x * 64;
    const int b = row0 >> 13;
    const int tid = threadIdx.x;

    for (int idx = tid; idx < NS * 96; idx += 128) {
        int s = idx & 31, jp = idx >> 5;
        float f0 = (2 * jp     < IN_DIM) ? g_KQT[2 * jp][b * NS + s]     : 0.f;
        float f1 = (2 * jp + 1 < IN_DIM) ? g_KQT[2 * jp + 1][b * NS + s] : 0.f;
        float h0 = bf16rt(f0), h1 = bf16rt(f1);
        khi[s * 100 + jp] = packbf2(h0, h1);
        klo[s * 100 + jp] = packbf2(f0 - h0, f1 - h1);
    }
    __syncthreads();

    const int warp = tid >> 5, lane = tid & 31;
    const int gid = lane >> 2, tig = lane & 3;
    const int wr = warp * 16;
    const float* xr0 = x + (size_t)(row0 + wr + gid) * IN_DIM;
    const float* xr1 = xr0 + 8 * IN_DIM;

    float c[4][4];
    #pragma unroll
    for (int nt = 0; nt < 4; nt++)
        #pragma unroll
        for (int q = 0; q < 4; q++) c[nt][q] = 0.f;

    const float2 z2 = make_float2(0.f, 0.f);
    #pragma unroll
    for (int kt = 0; kt < 12; kt++) {
        const int kb = kt * 16;
        const int k0 = kb + 2 * tig;
        const int k1 = kb + 8 + 2 * tig;
        float2 a00 = (k0 < 179) ? *(const float2*)(xr0 + k0) : z2;
        float2 a01 = (k1 < 179) ? *(const float2*)(xr0 + k1) : z2;
        float2 a10 = (k0 < 179) ? *(const float2*)(xr1 + k0) : z2;
        float2 a11 = (k1 < 179) ? *(const float2*)(xr1 + k1) : z2;

        u32 Ah[4], Al[4];
        {
            float hx = bf16rt(a00.x), hy = bf16rt(a00.y);
            Ah[0] = packbf2(hx, hy); Al[0] = packbf2(a00.x - hx, a00.y - hy);
        }
        {
            float hx = bf16rt(a10.x), hy = bf16rt(a10.y);
            Ah[1] = packbf2(hx, hy); Al[1] = packbf2(a10.x - hx, a10.y - hy);
        }
        {
            float hx = bf16rt(a01.x), hy = bf16rt(a01.y);
            Ah[2] = packbf2(hx, hy); Al[2] = packbf2(a01.x - hx, a01.y - hy);
        }
        {
            float hx = bf16rt(a11.x), hy = bf16rt(a11.y);
            Ah[3] = packbf2(hx, hy); Al[3] = packbf2(a11.x - hx, a11.y - hy);
        }

        const int pb = kt * 8;
        #pragma unroll
        for (int nt = 0; nt < 4; nt++) {
            const int n = nt * 8 + gid;
            u32 Bh[2] = { khi[n * 100 + pb + tig], khi[n * 100 + pb + tig + 4] };
            u32 Bl[2] = { klo[n * 100 + pb + tig], klo[n * 100 + pb + tig + 4] };
            mma16816(c[nt], Ah, Bh);
            mma16816(c[nt], Ah, Bl);
            mma16816(c[nt], Al, Bh);
        }
    }

    float m0 = -1e30f, m1 = -1e30f;
    #pragma unroll
    for (int nt = 0; nt < 4; nt++) {
        m0 = fmaxf(m0, fmaxf(c[nt][0], c[nt][1]));
        m1 = fmaxf(m1, fmaxf(c[nt][2], c[nt][3]));
    }
    m0 = fmaxf(m0, __shfl_xor_sync(0xffffffffu, m0, 1));
    m0 = fmaxf(m0, __shfl_xor_sync(0xffffffffu, m0, 2));
    m1 = fmaxf(m1, __shfl_xor_sync(0xffffffffu, m1, 1));
    m1 = fmaxf(m1, __shfl_xor_sync(0xffffffffu, m1, 2));

    float e[4][4];
    float s0 = 0.f, s1 = 0.f;
    #pragma unroll
    for (int nt = 0; nt < 4; nt++) {
        e[nt][0] = __expf(c[nt][0] - m0);
        e[nt][1] = __expf(c[nt][1] - m0);
        e[nt][2] = __expf(c[nt][2] - m1);
        e[nt][3] = __expf(c[nt][3] - m1);
        s0 += e[nt][0] + e[nt][1];
        s1 += e[nt][2] + e[nt][3];
    }
    s0 += __shfl_xor_sync(0xffffffffu, s0, 1);
    s0 += __shfl_xor_sync(0xffffffffu, s0, 2);
    s1 += __shfl_xor_sync(0xffffffffu, s1, 1);
    s1 += __shfl_xor_sync(0xffffffffu, s1, 2);
    float i0 = 1.0f / s0, i1 = 1.0f / s1;

    #pragma unroll
    for (int nt = 0; nt < 4; nt++) {
        const int n = nt * 8 + tig * 2;
        *(float2*)&w_out[(size_t)(row0 + wr + gid    ) * NS + n] =
            make_float2(e[nt][0] * i0, e[nt][1] * i0);
        *(float2*)&w_out[(size_t)(row0 + wr + gid + 8) * NS + n] =
            make_float2(e[nt][2] * i1, e[nt][3] * i1);
    }
}

// ---------------------------------------------------------------------------
// C2 (tensor core): s = w @ sl, bf16 3-term split, 2x A-reuse.
// (unchanged from the 104.5us run)
// ---------------------------------------------------------------------------
#define C2_SMEM 40960
__global__ __launch_bounds__(256, 3) void c2_kernel(const float* __restrict__ sl,
                                                    const float* __restrict__ w_in,
                                                    float* __restrict__ s_out) {
    extern __shared__ u32 c2sm[];
    u32* slT_hi = c2sm;              // [128][20]
    u32* slT_lo = c2sm + 2560;       // [128][20]
    u32* whi    = c2sm + 5120;       // [128][20]
    u32* wlo    = c2sm + 7680;       // [128][20]

    const int d0   = blockIdx.x * 128;
    const int row0 = blockIdx.y * 128;
    const int b    = row0 >> 13;
    const int tid  = threadIdx.x;

    #pragma unroll
    for (int t = 0; t < 8; t++) {
        int idx = t * 256 + tid;
        int q = idx >> 7, d = idx & 127;
        const float* base = &sl[(size_t)(b * NS + 2 * q) * SD + d0 + d];
        float v0 = base[0], v1 = base[SD];
        float h0 = bf16rt(v0), h1 = bf16rt(v1);
        slT_hi[d * 20 + q] = packbf2(h0, h1);
        slT_lo[d * 20 + q] = packbf2(v0 - h0, v1 - h1);
    }
    #pragma unroll
    for (int t = 0; t < 8; t++) {
        int idx = t * 256 + tid;
        int r = idx >> 4, q = idx & 15;
        const float* wb = &w_in[(size_t)(row0 + r) * NS + 2 * q];
        float v0 = wb[0], v1 = wb[1];
        float h0 = bf16rt(v0), h1 = bf16rt(v1);
        whi[r * 20 + q] = packbf2(h0, h1);
        wlo[r * 20 + q] = packbf2(v0 - h0, v1 - h1);
    }
    __syncthreads();

    const int warp = tid >> 5, lane = tid & 31;
    const int gid = lane >> 2, tig = lane & 3;
    const int wr = (warp >> 1) * 32;    // 0,32,64,96
    const int wd = (warp & 1) * 64;     // 0,64

    u32 Ah0[8], Al0[8], Ah1[8], Al1[8];
    #pragma unroll
    for (int k = 0; k < 2; k++) {
        int pb = k * 8;
        int r0a = wr + gid, r0b = wr + gid + 8;
        int r1a = r0a + 16, r1b = r0b + 16;
        Ah0[k*4+0] = whi[r0a * 20 + pb + tig];
        Ah0[k*4+1] = whi[r0b * 20 + pb + tig];
        Ah0[k*4+2] = whi[r0a * 20 + pb + tig + 4];
        Ah0[k*4+3] = whi[r0b * 20 + pb + tig + 4];
        Al0[k*4+0] = wlo[r0a * 20 + pb + tig];
        Al0[k*4+1] = wlo[r0b * 20 + pb + tig];
        Al0[k*4+2] = wlo[r0a * 20 + pb + tig + 4];
        Al0[k*4+3] = wlo[r0b * 20 + pb + tig + 4];
        Ah1[k*4+0] = whi[r1a * 20 + pb + tig];
        Ah1[k*4+1] = whi[r1b * 20 + pb + tig];
        Ah1[k*4+2] = whi[r1a * 20 + pb + tig + 4];
        Ah1[k*4+3] = whi[r1b * 20 + pb + tig + 4];
        Al1[k*4+0] = wlo[r1a * 20 + pb + tig];
        Al1[k*4+1] = wlo[r1b * 20 + pb + tig];
        Al1[k*4+2] = wlo[r1a * 20 + pb + tig + 4];
        Al1[k*4+3] = wlo[r1b * 20 + pb + tig + 4];
    }

    #pragma unroll
    for (int nt = 0; nt < 8; nt++) {
        const int dcol = wd + nt * 8 + gid;
        u32 Bh[4], Bl[4];
        Bh[0] = slT_hi[dcol * 20 + tig];      Bh[1] = slT_hi[dcol * 20 + tig + 4];
        Bh[2] = slT_hi[dcol * 20 + 8 + tig];  Bh[3] = slT_hi[dcol * 20 + 12 + tig];
        Bl[0] = slT_lo[dcol * 20 + tig];      Bl[1] = slT_lo[dcol * 20 + tig + 4];
        Bl[2] = slT_lo[dcol * 20 + 8 + tig];  Bl[3] = slT_lo[dcol * 20 + 12 + tig];

        float c0h[4] = {0.f, 0.f, 0.f, 0.f};
        float c0x[4] = {0.f, 0.f, 0.f, 0.f};
        float c1h[4] = {0.f, 0.f, 0.f, 0.f};
        float c1x[4] = {0.f, 0.f, 0.f, 0.f};
        mma16816(c0h, &Ah0[0], &Bh[0]);
        mma16816(c1h, &Ah1[0], &Bh[0]);
        mma16816(c0x, &Ah0[0], &Bl[0]);
        mma16816(c1x, &Ah1[0], &Bl[0]);
        mma16816(c0h, &Ah0[4], &Bh[2]);
        mma16816(c1h, &Ah1[4], &Bh[2]);
        mma16816(c0x, &Al0[0], &Bh[0]);
        mma16816(c1x, &Al1[0], &Bh[0]);
        mma16816(c0x, &Ah0[4], &Bl[2]);
        mma16816(c1x, &Ah1[4], &Bl[2]);
        mma16816(c0x, &Al0[4], &Bh[2]);
        mma16816(c1x, &Al1[4], &Bh[2]);

        const int dg = d0 + wd + nt * 8 + tig * 2;
        *(float2*)&s_out[(size_t)(row0 + wr + gid         ) * SD + dg] =
            make_float2(c0h[0] + c0x[0], c0h[1] + c0x[1]);
        *(float2*)&s_out[(size_t)(row0 + wr + gid + 8     ) * SD + dg] =
            make_float2(c0h[2] + c0x[2], c0h[3] + c0x[3]);
        *(float2*)&s_out[(size_t)(row0 + wr + gid + 16    ) * SD + dg] =
            make_float2(c1h[0] + c1x[0], c1h[1] + c1x[1]);
        *(float2*)&s_out[(size_t)(row0 + wr + gid + 24    ) * SD + dg] =
            make_float2(c1h[2] + c1x[2], c1h[3] + c1x[3]);
    }
}

// ---------------------------------------------------------------------------
extern "C" void kernel_launch(void* const* d_in, const int* in_sizes, int n_in,
                              void* d_out, int out_size) {
    const float* x  = (const float*)d_in[0];   // [4,8192,180]
    const float* sl = (const float*)d_in[1];   // [4,32,1536]
    const float* Wq = (const float*)d_in[2];   // [180,1536]
    const float* Wk = (const float*)d_in[3];   // [1536,1536]
    float* out   = (float*)d_out;
    float* s_out = out;                               // [4,8192,1536]
    float* w_out = out + (size_t)NB * NR * SD;        // [4,8192,32]

    static int attr_done = 0;
    if (!attr_done) {
        cudaFuncSetAttribute(p1m_kernel,
                             cudaFuncAttributeMaxDynamicSharedMemorySize, P1_SMEM);
        cudaFuncSetAttribute(c2_kernel,
                             cudaFuncAttributeMaxDynamicSharedMemorySize, C2_SMEM);
        attr_done = 1;
    }

    p1m_kernel<<<dim3(AD / 64, P1KC), 256, P1_SMEM>>>(sl, Wk);
    p1r_kernel<<<(BS * AD / 4) / 256, 256>>>();
    p2_kernel<<<dim3(192 / JT, AC), 256>>>(Wq);
    c1_kernel<<<(NB * NR) / 64, 128>>>(x, w_out);
    c2_kernel<<<dim3(SD / 128, (NB * NR) / 128), 256, C2_SMEM>>>(sl, w_out, s_out);
}

// round 17
// speedup vs baseline: 1.4088x; 1.0092x over previous
#include <cuda_runtime.h>
#include <cuda_bf16.h>

// ---------------------------------------------------------------------------
// MixingBlock: s = softmax((x Wq)(sl Wk)^T * scale) @ sl,  w = the softmax
// Restructure: dots = x @ KQ^T with KQ = scale * (sl Wk) Wq^T  (tiny [128,180])
// Pipeline: p1m (bf16 mma) -> p1r (reduce + zero KQT + sl pre-split)
//           -> p2 (atomic KQ) -> c1 (bf16 mma, also writes w pre-split)
//           -> c2 (bf16 mma, copy-only fills)
// ---------------------------------------------------------------------------

#define NB 4
#define NR 8192
#define NS 32
#define IN_DIM 180
#define SD 1536
#define AD 1536
#define BS (NB*NS)          // 128
#define P1KC 6              // k-chunks for p1m
#define P1KCHUNK (SD/P1KC)  // 256
#define AC 24               // a-chunks for p2
#define ACHUNK (AD/AC)      // 64
#define JT 16               // j-tile for p2

typedef unsigned long long ull;
typedef unsigned int u32;

__device__ float g_kp2[P1KC][BS][AD];     // p1m partials
__device__ float g_kred[BS][AD];          // reduced k
__device__ float g_KQT[IN_DIM][BS];       // KQ transposed (scale folded in)
__device__ u32   g_slhi[NB][SD][16];      // sl pre-split (packed bf16x2 pairs)
__device__ u32   g_sllo[NB][SD][16];
__device__ u32   g_whi[NB * NR][16];      // w pre-split (packed bf16x2 pairs)
__device__ u32   g_wlo[NB * NR][16];

// ---- packed f32x2 helpers -------------------------------------------------
__device__ __forceinline__ ull fpack(float x, float y) {
    ull r; asm("mov.b64 %0, {%1, %2};" : "=l"(r) : "f"(x), "f"(y)); return r;
}
__device__ __forceinline__ float2 funpack(ull v) {
    float2 r; asm("mov.b64 {%0, %1}, %2;" : "=f"(r.x), "=f"(r.y) : "l"(v)); return r;
}
__device__ __forceinline__ ull ffma2(ull a, ull b, ull c) {
    ull d; asm("fma.rn.f32x2 %0, %1, %2, %3;" : "=l"(d) : "l"(a), "l"(b), "l"(c)); return d;
}
__device__ __forceinline__ ull d2u(double d) { return __double_as_longlong(d); }
__device__ __forceinline__ double u2d(ull v) { return __longlong_as_double(v); }

// ---- bf16 helpers ---------------------------------------------------------
__device__ __forceinline__ u32 packbf2(float x, float y) {
    __nv_bfloat162 t = __floats2bfloat162_rn(x, y);
    return *reinterpret_cast<u32*>(&t);
}
__device__ __forceinline__ float bf16rt(float v) {
    return __bfloat162float(__float2bfloat16_rn(v));
}
__device__ __forceinline__ void mma16816(float c[4], const u32 a[4], const u32 b[2]) {
    asm volatile(
        "mma.sync.aligned.m16n8k16.row.col.f32.bf16.bf16.f32 "
        "{%0,%1,%2,%3},{%4,%5,%6,%7},{%8,%9},{%0,%1,%2,%3};"
        : "+f"(c[0]), "+f"(c[1]), "+f"(c[2]), "+f"(c[3])
        : "r"(a[0]), "r"(a[1]), "r"(a[2]), "r"(a[3]), "r"(b[0]), "r"(b[1]));
}

// ---------------------------------------------------------------------------
// P1M (tensor core): k = sl @ Wk  (M=128, N=1536, K=1536), bf16 3-term split.
// (unchanged from the 98.8us run)
// ---------------------------------------------------------------------------
#define P1_SMEM ((128*33*2 + 64*33*2) * 4)
__global__ __launch_bounds__(256, 2) void p1m_kernel(const float* __restrict__ sl,
                                                     const float* __restrict__ Wk) {
    extern __shared__ u32 p1sm[];
    u32* sAh = p1sm;                   // [128][33]
    u32* sAl = p1sm + 128 * 33;
    u32* sBh = p1sm + 2 * 128 * 33;    // [64][33]
    u32* sBl = p1sm + 2 * 128 * 33 + 64 * 33;

    const int n0  = blockIdx.x * 64;
    const int kc  = blockIdx.y;
    const int kc0 = kc * P1KCHUNK;
    const int tid = threadIdx.x;
    const int warp = tid >> 5, lane = tid & 31;
    const int gid = lane >> 2, tig = lane & 3;
    const int mw = warp * 16;

    float c[8][4];
    #pragma unroll
    for (int nt = 0; nt < 8; nt++)
        #pragma unroll
        for (int q = 0; q < 4; q++) c[nt][q] = 0.f;

    for (int sc = 0; sc < P1KCHUNK / 64; sc++) {
        const int kb = kc0 + sc * 64;
        __syncthreads();
        #pragma unroll
        for (int t = 0; t < 16; t++) {
            int idx = t * 256 + tid;
            int m = idx >> 5, kp = idx & 31;
            float2 v = *(const float2*)&sl[(size_t)m * SD + kb + 2 * kp];
            float hx = bf16rt(v.x), hy = bf16rt(v.y);
            sAh[m * 33 + kp] = packbf2(hx, hy);
            sAl[m * 33 + kp] = packbf2(v.x - hx, v.y - hy);
        }
        #pragma unroll
        for (int t = 0; t < 8; t++) {
            int idx = t * 256 + tid;
            int kp = idx >> 6, n = idx & 63;
            float v0 = Wk[(size_t)(kb + 2 * kp)     * AD + n0 + n];
            float v1 = Wk[(size_t)(kb + 2 * kp + 1) * AD + n0 + n];
            float h0 = bf16rt(v0), h1 = bf16rt(v1);
            sBh[n * 33 + kp] = packbf2(h0, h1);
            sBl[n * 33 + kp] = packbf2(v0 - h0, v1 - h1);
        }
        __syncthreads();

        #pragma unroll
        for (int ks = 0; ks < 4; ks++) {
            const int kp0 = ks * 8;
            u32 Ah[4], Al[4];
            Ah[0] = sAh[(mw + gid    ) * 33 + kp0 + tig];
            Ah[1] = sAh[(mw + gid + 8) * 33 + kp0 + tig];
            Ah[2] = sAh[(mw + gid    ) * 33 + kp0 + tig + 4];
            Ah[3] = sAh[(mw + gid + 8) * 33 + kp0 + tig + 4];
            Al[0] = sAl[(mw + gid    ) * 33 + kp0 + tig];
            Al[1] = sAl[(mw + gid + 8) * 33 + kp0 + tig];
            Al[2] = sAl[(mw + gid    ) * 33 + kp0 + tig + 4];
            Al[3] = sAl[(mw + gid + 8) * 33 + kp0 + tig + 4];
            #pragma unroll
            for (int nt = 0; nt < 8; nt++) {
                const int n = nt * 8 + gid;
                u32 Bh[2] = { sBh[n * 33 + kp0 + tig], sBh[n * 33 + kp0 + tig + 4] };
                u32 Bl[2] = { sBl[n * 33 + kp0 + tig], sBl[n * 33 + kp0 + tig + 4] };
                mma16816(c[nt], Ah, Bh);
                mma16816(c[nt], Ah, Bl);
                mma16816(c[nt], Al, Bh);
            }
        }
    }
    #pragma unroll
    for (int nt = 0; nt < 8; nt++) {
        const int dg = n0 + nt * 8 + tig * 2;
        *(float2*)&g_kp2[kc][mw + gid    ][dg] = make_float2(c[nt][0], c[nt][1]);
        *(float2*)&g_kp2[kc][mw + gid + 8][dg] = make_float2(c[nt][2], c[nt][3]);
    }
}

// ---------------------------------------------------------------------------
// P1R: g_kred = sum g_kp2; zeros g_KQT; NEW: pre-splits sl into g_slhi/lo.
// grid 192 x 256 thr.
// ---------------------------------------------------------------------------
__global__ __launch_bounds__(256) void p1r_kernel(const float* __restrict__ sl) {
    int gid = blockIdx.x * 256 + threadIdx.x;    // 0..49151
    if (gid < IN_DIM * BS) (&g_KQT[0][0])[gid] = 0.f;
    const float4* src = (const float4*)&g_kp2[0][0][0];
    float4* dst = (float4*)&g_kred[0][0];
    const int stride = (BS * AD) / 4;
    float4 a = make_float4(0.f, 0.f, 0.f, 0.f);
    #pragma unroll
    for (int p = 0; p < P1KC; p++) {
        float4 v = src[(size_t)p * stride + gid];
        a.x += v.x; a.y += v.y; a.z += v.z; a.w += v.w;
    }
    dst[gid] = a;

    // sl pre-split: 4b x 1536d x 16q = 98304 entries, 2 per thread
    #pragma unroll
    for (int t = 0; t < 2; t++) {
        int idx = t * 49152 + gid;               // 0..98303
        int b = idx / (SD * 16);
        int rem = idx - b * SD * 16;
        int d = rem >> 4, q = rem & 15;
        float v0 = sl[(size_t)(b * NS + 2 * q)     * SD + d];
        float v1 = sl[(size_t)(b * NS + 2 * q + 1) * SD + d];
        float h0 = bf16rt(v0), h1 = bf16rt(v1);
        g_slhi[b][d][q] = packbf2(h0, h1);
        g_sllo[b][d][q] = packbf2(v0 - h0, v1 - h1);
    }
}

// ---------------------------------------------------------------------------
// P2: g_KQT[j][m] += scale * sum_{a in chunk} kred[m][a] * Wq[j][a]
// (unchanged, proven)
// ---------------------------------------------------------------------------
__global__ __launch_bounds__(256) void p2_kernel(const float* __restrict__ Wq) {
    const int j0 = blockIdx.x * JT;
    const int ac = blockIdx.y;
    const int a0 = ac * ACHUNK;
    __shared__ float ksm[64][130];
    __shared__ ull   wqs[64][18];
    const int tid = threadIdx.x;
    const int mp = tid & 63;
    const int jg = tid >> 6;

    #pragma unroll
    for (int t = 0; t < 8; t++) {
        int idx = t * 256 + tid;
        int m = idx >> 4, aq = idx & 15;
        float4 v = *(const float4*)&g_kred[m][a0 + aq * 4];
        ksm[aq * 4 + 0][m] = v.x;
        ksm[aq * 4 + 1][m] = v.y;
        ksm[aq * 4 + 2][m] = v.z;
        ksm[aq * 4 + 3][m] = v.w;
    }
    const float scale = rsqrtf((float)AD);
    #pragma unroll
    for (int t = 0; t < 4; t++) {
        int idx = t * 256 + tid;
        int jj = idx >> 6, a = idx & 63;
        int j = j0 + jj;
        float v = (j < IN_DIM) ? Wq[(size_t)j * AD + a0 + a] * scale : 0.f;
        wqs[a][jj] = fpack(v, v);
    }
    __syncthreads();

    ull acc[4] = {0ULL, 0ULL, 0ULL, 0ULL};
    #pragma unroll 4
    for (int a = 0; a < ACHUNK; a++) {
        ull kp = *(const ull*)&ksm[a][2 * mp];
        double2 w01 = *(const double2*)&wqs[a][jg * 4];
        double2 w23 = *(const double2*)&wqs[a][jg * 4 + 2];
        acc[0] = ffma2(kp, d2u(w01.x), acc[0]);
        acc[1] = ffma2(kp, d2u(w01.y), acc[1]);
        acc[2] = ffma2(kp, d2u(w23.x), acc[2]);
        acc[3] = ffma2(kp, d2u(w23.y), acc[3]);
    }
    #pragma unroll
    for (int q = 0; q < 4; q++) {
        int j = j0 + jg * 4 + q;
        if (j < IN_DIM) {
            float2 v = funpack(acc[q]);
            atomicAdd(&g_KQT[j][2 * mp], v.x);
            atomicAdd(&g_KQT[j][2 * mp + 1], v.y);
        }
    }
}

// ---------------------------------------------------------------------------
// C1 (tensor core): dots = x @ KQ, softmax, write w.
// NEW: also writes pre-split packed w (g_whi/g_wlo) in fragment pair order.
// ---------------------------------------------------------------------------
__global__ __launch_bounds__(128, 6) void c1_kernel(const float* __restrict__ x,
                                                    float* __restrict__ w_out) {
    __shared__ u32 khi[NS * 100];
    __shared__ u32 klo[NS * 100];

    const int row0 = blockIdx.x * 64;
    const int b = row0 >> 13;
    const int tid = threadIdx.x;

    for (int idx = tid; idx < NS * 96; idx += 128) {
        int s = idx & 31, jp = idx >> 5;
        float f0 = (2 * jp     < IN_DIM) ? g_KQT[2 * jp][b * NS + s]     : 0.f;
        float f1 = (2 * jp + 1 < IN_DIM) ? g_KQT[2 * jp + 1][b * NS + s] : 0.f;
        float h0 = bf16rt(f0), h1 = bf16rt(f1);
        khi[s * 100 + jp] = packbf2(h0, h1);
        klo[s * 100 + jp] = packbf2(f0 - h0, f1 - h1);
    }
    __syncthreads();

    const int warp = tid >> 5, lane = tid & 31;
    const int gid = lane >> 2, tig = lane & 3;
    const int wr = warp * 16;
    const float* xr0 = x + (size_t)(row0 + wr + gid) * IN_DIM;
    const float* xr1 = xr0 + 8 * IN_DIM;

    float c[4][4];
    #pragma unroll
    for (int nt = 0; nt < 4; nt++)
        #pragma unroll
        for (int q = 0; q < 4; q++) c[nt][q] = 0.f;

    const float2 z2 = make_float2(0.f, 0.f);
    #pragma unroll
    for (int kt = 0; kt < 12; kt++) {
        const int kb = kt * 16;
        const int k0 = kb + 2 * tig;
        const int k1 = kb + 8 + 2 * tig;
        float2 a00 = (k0 < 179) ? *(const float2*)(xr0 + k0) : z2;
        float2 a01 = (k1 < 179) ? *(const float2*)(xr0 + k1) : z2;
        float2 a10 = (k0 < 179) ? *(const float2*)(xr1 + k0) : z2;
        float2 a11 = (k1 < 179) ? *(const float2*)(xr1 + k1) : z2;

        u32 Ah[4], Al[4];
        {
            float hx = bf16rt(a00.x), hy = bf16rt(a00.y);
            Ah[0] = packbf2(hx, hy); Al[0] = packbf2(a00.x - hx, a00.y - hy);
        }
        {
            float hx = bf16rt(a10.x), hy = bf16rt(a10.y);
            Ah[1] = packbf2(hx, hy); Al[1] = packbf2(a10.x - hx, a10.y - hy);
        }
        {
            float hx = bf16rt(a01.x), hy = bf16rt(a01.y);
            Ah[2] = packbf2(hx, hy); Al[2] = packbf2(a01.x - hx, a01.y - hy);
        }
        {
            float hx = bf16rt(a11.x), hy = bf16rt(a11.y);
            Ah[3] = packbf2(hx, hy); Al[3] = packbf2(a11.x - hx, a11.y - hy);
        }

        const int pb = kt * 8;
        #pragma unroll
        for (int nt = 0; nt < 4; nt++) {
            const int n = nt * 8 + gid;
            u32 Bh[2] = { khi[n * 100 + pb + tig], khi[n * 100 + pb + tig + 4] };
            u32 Bl[2] = { klo[n * 100 + pb + tig], klo[n * 100 + pb + tig + 4] };
            mma16816(c[nt], Ah, Bh);
            mma16816(c[nt], Ah, Bl);
            mma16816(c[nt], Al, Bh);
        }
    }

    float m0 = -1e30f, m1 = -1e30f;
    #pragma unroll
    for (int nt = 0; nt < 4; nt++) {
        m0 = fmaxf(m0, fmaxf(c[nt][0], c[nt][1]));
        m1 = fmaxf(m1, fmaxf(c[nt][2], c[nt][3]));
    }
    m0 = fmaxf(m0, __shfl_xor_sync(0xffffffffu, m0, 1));
    m0 = fmaxf(m0, __shfl_xor_sync(0xffffffffu, m0, 2));
    m1 = fmaxf(m1, __shfl_xor_sync(0xffffffffu, m1, 1));
    m1 = fmaxf(m1, __shfl_xor_sync(0xffffffffu, m1, 2));

    float e[4][4];
    float s0 = 0.f, s1 = 0.f;
    #pragma unroll
    for (int nt = 0; nt < 4; nt++) {
        e[nt][0] = __expf(c[nt][0] - m0);
        e[nt][1] = __expf(c[nt][1] - m0);
        e[nt][2] = __expf(c[nt][2] - m1);
        e[nt][3] = __expf(c[nt][3] - m1);
        s0 += e[nt][0] + e[nt][1];
        s1 += e[nt][2] + e[nt][3];
    }
    s0 += __shfl_xor_sync(0xffffffffu, s0, 1);
    s0 += __shfl_xor_sync(0xffffffffu, s0, 2);
    s1 += __shfl_xor_sync(0xffffffffu, s1, 1);
    s1 += __shfl_xor_sync(0xffffffffu, s1, 2);
    float i0 = 1.0f / s0, i1 = 1.0f / s1;

    const int r0g = row0 + wr + gid;
    const int r1g = r0g + 8;
    #pragma unroll
    for (int nt = 0; nt < 4; nt++) {
        const int n = nt * 8 + tig * 2;
        float wa = e[nt][0] * i0, wb = e[nt][1] * i0;
        float wc = e[nt][2] * i1, wd = e[nt][3] * i1;
        *(float2*)&w_out[(size_t)r0g * NS + n] = make_float2(wa, wb);
        *(float2*)&w_out[(size_t)r1g * NS + n] = make_float2(wc, wd);
        // pre-split packed (pair index nt*4+tig = n/2)
        float ha = bf16rt(wa), hb = bf16rt(wb);
        float hc = bf16rt(wc), hd = bf16rt(wd);
        g_whi[r0g][nt * 4 + tig] = packbf2(ha, hb);
        g_wlo[r0g][nt * 4 + tig] = packbf2(wa - ha, wb - hb);
        g_whi[r1g][nt * 4 + tig] = packbf2(hc, hd);
        g_wlo[r1g][nt * 4 + tig] = packbf2(wc - hc, wd - hd);
    }
}

// ---------------------------------------------------------------------------
// C2 (tensor core): s = w @ sl, bf16 3-term split, 2x A-reuse.
// NEW: fills are pure u32 copies from pre-split g_slhi/lo + g_whi/lo.
// ---------------------------------------------------------------------------
#define C2_SMEM 40960
__global__ __launch_bounds__(256, 3) void c2_kernel(float* __restrict__ s_out) {
    extern __shared__ u32 c2sm[];
    u32* slT_hi = c2sm;              // [128][20]
    u32* slT_lo = c2sm + 2560;       // [128][20]
    u32* whi    = c2sm + 5120;       // [128][20]
    u32* wlo    = c2sm + 7680;       // [128][20]

    const int d0   = blockIdx.x * 128;
    const int row0 = blockIdx.y * 128;
    const int b    = row0 >> 13;
    const int tid  = threadIdx.x;

    #pragma unroll
    for (int t = 0; t < 8; t++) {    // sl tiles: copy 2048 u32 each
        int idx = t * 256 + tid;
        int d = idx >> 4, q = idx & 15;
        slT_hi[d * 20 + q] = g_slhi[b][d0 + d][q];
        slT_lo[d * 20 + q] = g_sllo[b][d0 + d][q];
    }
    #pragma unroll
    for (int t = 0; t < 8; t++) {    // w tiles: copy 2048 u32 each
        int idx = t * 256 + tid;
        int r = idx >> 4, q = idx & 15;
        whi[r * 20 + q] = g_whi[row0 + r][q];
        wlo[r * 20 + q] = g_wlo[row0 + r][q];
    }
    __syncthreads();

    const int warp = tid >> 5, lane = tid & 31;
    const int gid = lane >> 2, tig = lane & 3;
    const int wr = (warp >> 1) * 32;    // 0,32,64,96
    const int wd = (warp & 1) * 64;     // 0,64

    u32 Ah0[8], Al0[8], Ah1[8], Al1[8];
    #pragma unroll
    for (int k = 0; k < 2; k++) {
        int pb = k * 8;
        int r0a = wr + gid, r0b = wr + gid + 8;
        int r1a = r0a + 16, r1b = r0b + 16;
        Ah0[k*4+0] = whi[r0a * 20 + pb + tig];
        Ah0[k*4+1] = whi[r0b * 20 + pb + tig];
        Ah0[k*4+2] = whi[r0a * 20 + pb + tig + 4];
        Ah0[k*4+3] = whi[r0b * 20 + pb + tig + 4];
        Al0[k*4+0] = wlo[r0a * 20 + pb + tig];
        Al0[k*4+1] = wlo[r0b * 20 + pb + tig];
        Al0[k*4+2] = wlo[r0a * 20 + pb + tig + 4];
        Al0[k*4+3] = wlo[r0b * 20 + pb + tig + 4];
        Ah1[k*4+0] = whi[r1a * 20 + pb + tig];
        Ah1[k*4+1] = whi[r1b * 20 + pb + tig];
        Ah1[k*4+2] = whi[r1a * 20 + pb + tig + 4];
        Ah1[k*4+3] = whi[r1b * 20 + pb + tig + 4];
        Al1[k*4+0] = wlo[r1a * 20 + pb + tig];
        Al1[k*4+1] = wlo[r1b * 20 + pb + tig];
        Al1[k*4+2] = wlo[r1a * 20 + pb + tig + 4];
        Al1[k*4+3] = wlo[r1b * 20 + pb + tig + 4];
    }

    #pragma unroll
    for (int nt = 0; nt < 8; nt++) {
        const int dcol = wd + nt * 8 + gid;
        u32 Bh[4], Bl[4];
        Bh[0] = slT_hi[dcol * 20 + tig];      Bh[1] = slT_hi[dcol * 20 + tig + 4];
        Bh[2] = slT_hi[dcol * 20 + 8 + tig];  Bh[3] = slT_hi[dcol * 20 + 12 + tig];
        Bl[0] = slT_lo[dcol * 20 + tig];      Bl[1] = slT_lo[dcol * 20 + tig + 4];
        Bl[2] = slT_lo[dcol * 20 + 8 + tig];  Bl[3] = slT_lo[dcol * 20 + 12 + tig];

        float c0h[4] = {0.f, 0.f, 0.f, 0.f};
        float c0x[4] = {0.f, 0.f, 0.f, 0.f};
        float c1h[4] = {0.f, 0.f, 0.f, 0.f};
        float c1x[4] = {0.f, 0.f, 0.f, 0.f};
        mma16816(c0h, &Ah0[0], &Bh[0]);
        mma16816(c1h, &Ah1[0], &Bh[0]);
        mma16816(c0x, &Ah0[0], &Bl[0]);
        mma16816(c1x, &Ah1[0], &Bl[0]);
        mma16816(c0h, &Ah0[4], &Bh[2]);
        mma16816(c1h, &Ah1[4], &Bh[2]);
        mma16816(c0x, &Al0[0], &Bh[0]);
        mma16816(c1x, &Al1[0], &Bh[0]);
        mma16816(c0x, &Ah0[4], &Bl[2]);
        mma16816(c1x, &Ah1[4], &Bl[2]);
        mma16816(c0x, &Al0[4], &Bh[2]);
        mma16816(c1x, &Al1[4], &Bh[2]);

        const int dg = d0 + wd + nt * 8 + tig * 2;
        *(float2*)&s_out[(size_t)(row0 + wr + gid         ) * SD + dg] =
            make_float2(c0h[0] + c0x[0], c0h[1] + c0x[1]);
        *(float2*)&s_out[(size_t)(row0 + wr + gid + 8     ) * SD + dg] =
            make_float2(c0h[2] + c0x[2], c0h[3] + c0x[3]);
        *(float2*)&s_out[(size_t)(row0 + wr + gid + 16    ) * SD + dg] =
            make_float2(c1h[0] + c1x[0], c1h[1] + c1x[1]);
        *(float2*)&s_out[(size_t)(row0 + wr + gid + 24    ) * SD + dg] =
            make_float2(c1h[2] + c1x[2], c1h[3] + c1x[3]);
    }
}

// ---------------------------------------------------------------------------
extern "C" void kernel_launch(void* const* d_in, const int* in_sizes, int n_in,
                              void* d_out, int out_size) {
    const float* x  = (const float*)d_in[0];   // [4,8192,180]
    const float* sl = (const float*)d_in[1];   // [4,32,1536]
    const float* Wq = (const float*)d_in[2];   // [180,1536]
    const float* Wk = (const float*)d_in[3];   // [1536,1536]
    float* out   = (float*)d_out;
    float* s_out = out;                               // [4,8192,1536]
    float* w_out = out + (size_t)NB * NR * SD;        // [4,8192,32]

    static int attr_done = 0;
    if (!attr_done) {
        cudaFuncSetAttribute(p1m_kernel,
                             cudaFuncAttributeMaxDynamicSharedMemorySize, P1_SMEM);
        cudaFuncSetAttribute(c2_kernel,
                             cudaFuncAttributeMaxDynamicSharedMemorySize, C2_SMEM);
        attr_done = 1;
    }

    p1m_kernel<<<dim3(AD / 64, P1KC), 256, P1_SMEM>>>(sl, Wk);
    p1r_kernel<<<(BS * AD / 4) / 256, 256>>>(sl);
    p2_kernel<<<dim3(192 / JT, AC), 256>>>(Wq);
    c1_kernel<<<(NB * NR) / 64, 128>>>(x, w_out);
    c2_kernel<<<dim3(SD / 128, (NB * NR) / 128), 256, C2_SMEM>>>(s_out);
}